// round 1
// baseline (speedup 1.0000x reference)
#include <cuda_runtime.h>
#include <mma.h>

using namespace nvcuda;

// Problem constants
#define CB   128
#define CN1  256
#define CN2  256
#define CD   256
#define CH   8
#define CDH  32
#define CDFF 1024

// ---------------- scratch (device globals; no allocation allowed) ----------------
__device__ float g_q  [CB * CN1 * CD];
__device__ float g_k1 [CB * CN1 * CD];
__device__ float g_v1 [CB * CN1 * CD];
__device__ float g_k2 [CB * CN2 * CD];
__device__ float g_v2 [CB * CN2 * CD];
__device__ float g_ctx[CB * CN1 * CD];
__device__ float g_tmp[CB * CN1 * CD];
__device__ float g_o1 [CB * CN1 * CD];
__device__ float g_hid[CB * CN1 * CDFF];

typedef wmma::fragment<wmma::matrix_a, 16, 16, 8, wmma::precision::tf32, wmma::row_major> AFrag;
typedef wmma::fragment<wmma::matrix_b, 16, 16, 8, wmma::precision::tf32, wmma::row_major> BFragR;
typedef wmma::fragment<wmma::matrix_b, 16, 16, 8, wmma::precision::tf32, wmma::col_major> BFragC;
typedef wmma::fragment<wmma::accumulator, 16, 16, 8, float> CFrag;

template <typename F>
__device__ __forceinline__ void frag_to_tf32(F& f) {
#pragma unroll
    for (int i = 0; i < f.num_elements; i++) f.x[i] = wmma::__float_to_tf32(f.x[i]);
}

// ============================================================================
// Generic tf32 GEMM: C[M,N] = A[M,K] @ W[K,N] + bias (EPI==1: ReLU)
// Block tile 128x64, BK=32, 8 warps (4x2), each warp 32x32 (2x2 wmma tiles).
// ============================================================================
template <int EPI>
__global__ __launch_bounds__(256)
void gemm_tf32(const float* __restrict__ A, const float* __restrict__ W,
               const float* __restrict__ bias, float* __restrict__ C,
               int M, int N, int K)
{
    __shared__ float smem[128 * 68];            // reused as epilogue stage
    float* As = smem;                            // [128][36]
    float* Ws = smem + 128 * 36;                 // [32][68]

    const int tid  = threadIdx.x;
    const int warp = tid >> 5;
    const int wm   = warp & 3;                   // 0..3 (row group of 32)
    const int wn   = warp >> 2;                  // 0..1 (col group of 32)
    const int m0   = blockIdx.y * 128;
    const int n0   = blockIdx.x * 64;

    CFrag acc[2][2];
#pragma unroll
    for (int i = 0; i < 2; i++)
#pragma unroll
        for (int j = 0; j < 2; j++) wmma::fill_fragment(acc[i][j], 0.0f);

    for (int k0 = 0; k0 < K; k0 += 32) {
        // A tile: 128x32 = 1024 float4
#pragma unroll
        for (int i = tid; i < 1024; i += 256) {
            int r = i >> 3, c4 = i & 7;
            float4 v = *(const float4*)(A + (size_t)(m0 + r) * K + k0 + c4 * 4);
            float* d = As + r * 36 + c4 * 4;
            d[0] = v.x; d[1] = v.y; d[2] = v.z; d[3] = v.w;
        }
        // W tile: 32x64 = 512 float4
#pragma unroll
        for (int i = tid; i < 512; i += 256) {
            int r = i >> 4, c4 = i & 15;
            float4 v = *(const float4*)(W + (size_t)(k0 + r) * N + n0 + c4 * 4);
            float* d = Ws + r * 68 + c4 * 4;
            d[0] = v.x; d[1] = v.y; d[2] = v.z; d[3] = v.w;
        }
        __syncthreads();

#pragma unroll
        for (int kk = 0; kk < 32; kk += 8) {
            AFrag  af[2];
            BFragR bf[2];
#pragma unroll
            for (int i = 0; i < 2; i++) {
                wmma::load_matrix_sync(af[i], As + (wm * 32 + i * 16) * 36 + kk, 36);
                frag_to_tf32(af[i]);
            }
#pragma unroll
            for (int j = 0; j < 2; j++) {
                wmma::load_matrix_sync(bf[j], Ws + kk * 68 + wn * 32 + j * 16, 68);
                frag_to_tf32(bf[j]);
            }
#pragma unroll
            for (int i = 0; i < 2; i++)
#pragma unroll
                for (int j = 0; j < 2; j++)
                    wmma::mma_sync(acc[i][j], af[i], bf[j], acc[i][j]);
        }
        __syncthreads();
    }

    // Epilogue through shared stage (stride 68)
    float* stage = smem;
#pragma unroll
    for (int i = 0; i < 2; i++)
#pragma unroll
        for (int j = 0; j < 2; j++)
            wmma::store_matrix_sync(stage + (wm * 32 + i * 16) * 68 + wn * 32 + j * 16,
                                    acc[i][j], 68, wmma::mem_row_major);
    __syncthreads();

#pragma unroll
    for (int i = tid; i < 128 * 64; i += 256) {
        int r = i >> 6, c = i & 63;
        float v = stage[r * 68 + c] + bias[n0 + c];
        if (EPI == 1) v = fmaxf(v, 0.0f);
        C[(size_t)(m0 + r) * N + n0 + c] = v;
    }
}

// ============================================================================
// Fused dual-source graph attention.
// Grid: (N1/64, H, B). Block: 256 threads (8 warps).
// Per block: 64 query rows x (256 keys from x1 masked by adj1*mask1, softmax,
// P@V) + (256 keys from x2 masked by mask2, softmax, P@V), contexts summed.
// ============================================================================
#define SM_Q  (64 * 32)
#define SM_K  (256 * 32)
#define SM_V  (256 * 32)
#define SM_S  (64 * 264)
#define SMEM_ATTN_FLOATS (SM_Q + SM_K + SM_V + SM_S)
#define SMEM_ATTN_BYTES  (SMEM_ATTN_FLOATS * 4)

__global__ __launch_bounds__(256)
void attn_kernel(const float* __restrict__ Q,  const float* __restrict__ K1,
                 const float* __restrict__ V1, const float* __restrict__ K2,
                 const float* __restrict__ V2, const float* __restrict__ adj1,
                 const float* __restrict__ mask1, const float* __restrict__ mask2,
                 float* __restrict__ ctx)
{
    extern __shared__ float sm[];
    float* sQ = sm;
    float* sK = sQ + SM_Q;
    float* sV = sK + SM_K;
    float* sS = sV + SM_V;

    const int b  = blockIdx.z;
    const int h  = blockIdx.y;
    const int q0 = blockIdx.x * 64;
    const int tid  = threadIdx.x;
    const int warp = tid >> 5;
    const float scale = 0.17677669529663687f;   // 1/sqrt(32)

    // load Q tile (64x32) for this head
#pragma unroll
    for (int i = tid; i < 512; i += 256) {
        int r = i >> 3, c4 = i & 7;
        float4 v = *(const float4*)(Q + ((size_t)(b * CN1 + q0 + r) * CD + h * CDH + c4 * 4));
        float* d = sQ + r * 32 + c4 * 4;
        d[0] = v.x; d[1] = v.y; d[2] = v.z; d[3] = v.w;
    }

    // persistent context accumulator: warp -> (row tile, col tile)
    const int rt = warp >> 1;     // 0..3: rows [rt*16, +16)
    const int ct = warp & 1;      // 0..1: cols [ct*16, +16)
    CFrag cacc;
    wmma::fill_fragment(cacc, 0.0f);

#pragma unroll 1
    for (int src = 0; src < 2; src++) {
        const float* Kp = src ? K2 : K1;
        const float* Vp = src ? V2 : V1;

        // load K, V tiles (256x32 each)
#pragma unroll
        for (int i = tid; i < 2048; i += 256) {
            int r = i >> 3, c4 = i & 7;
            size_t gi = (size_t)(b * 256 + r) * CD + h * CDH + c4 * 4;
            float4 kv = *(const float4*)(Kp + gi);
            float4 vv = *(const float4*)(Vp + gi);
            float* dk = sK + r * 32 + c4 * 4;
            float* dv = sV + r * 32 + c4 * 4;
            dk[0] = kv.x; dk[1] = kv.y; dk[2] = kv.z; dk[3] = kv.w;
            dv[0] = vv.x; dv[1] = vv.y; dv[2] = vv.z; dv[3] = vv.w;
        }
        __syncthreads();

        // S = Q @ K^T   (64x256). warp: row tile (warp>>1), 8 col tiles at (warp&1)*128
        {
            const int srt   = warp >> 1;
            const int cbase = (warp & 1) * 128;
            CFrag accs[8];
#pragma unroll
            for (int c = 0; c < 8; c++) wmma::fill_fragment(accs[c], 0.0f);
#pragma unroll
            for (int kk = 0; kk < 32; kk += 8) {
                AFrag af;
                wmma::load_matrix_sync(af, sQ + (srt * 16) * 32 + kk, 32);
                frag_to_tf32(af);
#pragma unroll
                for (int c = 0; c < 8; c++) {
                    BFragC bf;
                    wmma::load_matrix_sync(bf, sK + (cbase + c * 16) * 32 + kk, 32);
                    frag_to_tf32(bf);
                    wmma::mma_sync(accs[c], af, bf, accs[c]);
                }
            }
#pragma unroll
            for (int c = 0; c < 8; c++)
                wmma::store_matrix_sync(sS + (srt * 16) * 264 + cbase + c * 16,
                                        accs[c], 264, wmma::mem_row_major);
        }
        __syncthreads();

        // masked softmax: 4 threads per row, 64 cols each
        {
            const int r  = tid >> 2;
            const int qd = tid & 3;
            const int grow = q0 + r;
            float* srow = sS + r * 264 + qd * 64;
            float mx = -1e30f;
            if (src == 0) {
                const float* adjrow = adj1 + ((size_t)b * CN1 + grow) * CN1 + qd * 64;
                const float* m1row  = mask1 + (size_t)b * CN1 + qd * 64;
#pragma unroll 8
                for (int j = 0; j < 64; j++) {
                    float s = srow[j] * scale;
                    float m = adjrow[j] * m1row[j];
                    s = (m > 0.0f) ? s : -1e9f;
                    srow[j] = s;
                    mx = fmaxf(mx, s);
                }
            } else {
                const float* m2row = mask2 + (size_t)b * CN2 + qd * 64;
#pragma unroll 8
                for (int j = 0; j < 64; j++) {
                    float s = srow[j] * scale;
                    s = (m2row[j] > 0.0f) ? s : -1e9f;
                    srow[j] = s;
                    mx = fmaxf(mx, s);
                }
            }
            mx = fmaxf(mx, __shfl_xor_sync(0xffffffffu, mx, 1));
            mx = fmaxf(mx, __shfl_xor_sync(0xffffffffu, mx, 2));
            float sum = 0.0f;
#pragma unroll 8
            for (int j = 0; j < 64; j++) {
                float e = __expf(srow[j] - mx);
                srow[j] = e;
                sum += e;
            }
            sum += __shfl_xor_sync(0xffffffffu, sum, 1);
            sum += __shfl_xor_sync(0xffffffffu, sum, 2);
            float inv = 1.0f / sum;
#pragma unroll 8
            for (int j = 0; j < 64; j++) srow[j] *= inv;
        }
        __syncthreads();

        // ctx += P @ V  (64x256)@(256x32)
#pragma unroll
        for (int kk = 0; kk < 256; kk += 8) {
            AFrag af;
            wmma::load_matrix_sync(af, sS + (rt * 16) * 264 + kk, 264);
            frag_to_tf32(af);
            BFragR bf;
            wmma::load_matrix_sync(bf, sV + kk * 32 + ct * 16, 32);
            frag_to_tf32(bf);
            wmma::mma_sync(cacc, af, bf, cacc);
        }
        __syncthreads();   // protect sK/sV/sS for next source
    }

    // store summed context directly to global [B,N1,D]
    float* out = ctx + ((size_t)(b * CN1 + q0 + rt * 16) * CD + h * CDH + ct * 16);
    wmma::store_matrix_sync(out, cacc, CD, wmma::mem_row_major);
}

// ============================================================================
// out = LayerNorm(X + Y) * g + be   (row length 256, one warp per row)
// ============================================================================
__global__ __launch_bounds__(256)
void add_ln_kernel(const float* __restrict__ X, const float* __restrict__ Y,
                   const float* __restrict__ g, const float* __restrict__ be,
                   float* __restrict__ out)
{
    const int warp = threadIdx.x >> 5;
    const int lane = threadIdx.x & 31;
    const size_t row = (size_t)blockIdx.x * 8 + warp;
    const float* x = X + row * CD;
    const float* y = Y + row * CD;

    float v[8];
    float s = 0.0f;
#pragma unroll
    for (int i = 0; i < 8; i++) {
        v[i] = x[lane + i * 32] + y[lane + i * 32];
        s += v[i];
    }
#pragma unroll
    for (int o = 16; o > 0; o >>= 1) s += __shfl_xor_sync(0xffffffffu, s, o);
    const float mu = s * (1.0f / CD);

    float s2 = 0.0f;
#pragma unroll
    for (int i = 0; i < 8; i++) {
        float d = v[i] - mu;
        s2 += d * d;
    }
#pragma unroll
    for (int o = 16; o > 0; o >>= 1) s2 += __shfl_xor_sync(0xffffffffu, s2, o);
    const float inv = rsqrtf(s2 * (1.0f / CD) + 1e-6f);

#pragma unroll
    for (int i = 0; i < 8; i++) {
        int c = lane + i * 32;
        out[row * CD + c] = g[c] * (v[i] - mu) * inv + be[c];
    }
}

// ============================================================================
// Host launch
// ============================================================================
extern "C" void kernel_launch(void* const* d_in, const int* in_sizes, int n_in,
                              void* d_out, int out_size)
{
    const float* x1    = (const float*)d_in[0];
    const float* adj1  = (const float*)d_in[1];
    const float* mask1 = (const float*)d_in[2];
    const float* x2    = (const float*)d_in[3];
    const float* mask2 = (const float*)d_in[4];
    const float* Wq = (const float*)d_in[5];  const float* bq = (const float*)d_in[6];
    const float* Wk = (const float*)d_in[7];  const float* bk = (const float*)d_in[8];
    const float* Wv = (const float*)d_in[9];  const float* bv = (const float*)d_in[10];
    const float* Wo = (const float*)d_in[11]; const float* bo = (const float*)d_in[12];
    const float* W1 = (const float*)d_in[13]; const float* b1 = (const float*)d_in[14];
    const float* W2 = (const float*)d_in[15]; const float* b2 = (const float*)d_in[16];
    const float* g1 = (const float*)d_in[17]; const float* be1 = (const float*)d_in[18];
    const float* g2 = (const float*)d_in[19]; const float* be2 = (const float*)d_in[20];
    float* out = (float*)d_out;

    float *q, *k1, *v1, *k2, *v2, *ctx, *tmp, *o1, *hid;
    cudaGetSymbolAddress((void**)&q,   g_q);
    cudaGetSymbolAddress((void**)&k1,  g_k1);
    cudaGetSymbolAddress((void**)&v1,  g_v1);
    cudaGetSymbolAddress((void**)&k2,  g_k2);
    cudaGetSymbolAddress((void**)&v2,  g_v2);
    cudaGetSymbolAddress((void**)&ctx, g_ctx);
    cudaGetSymbolAddress((void**)&tmp, g_tmp);
    cudaGetSymbolAddress((void**)&o1,  g_o1);
    cudaGetSymbolAddress((void**)&hid, g_hid);

    cudaFuncSetAttribute(attn_kernel, cudaFuncAttributeMaxDynamicSharedMemorySize,
                         SMEM_ATTN_BYTES);

    const int M = CB * CN1;          // 32768
    dim3 blk(256);

    // QKV projections
    gemm_tf32<0><<<dim3(CD / 64, M / 128), blk>>>(x1, Wq, bq, q,  M, CD, CD);
    gemm_tf32<0><<<dim3(CD / 64, M / 128), blk>>>(x1, Wk, bk, k1, M, CD, CD);
    gemm_tf32<0><<<dim3(CD / 64, M / 128), blk>>>(x1, Wv, bv, v1, M, CD, CD);
    gemm_tf32<0><<<dim3(CD / 64, M / 128), blk>>>(x2, Wk, bk, k2, M, CD, CD);
    gemm_tf32<0><<<dim3(CD / 64, M / 128), blk>>>(x2, Wv, bv, v2, M, CD, CD);

    // fused dual-source attention -> ctx (= c1 + c2, [B,N1,D])
    attn_kernel<<<dim3(CN1 / 64, CH, CB), blk, SMEM_ATTN_BYTES>>>(
        q, k1, v1, k2, v2, adj1, mask1, mask2, ctx);

    // output projection + residual LN
    gemm_tf32<0><<<dim3(CD / 64, M / 128), blk>>>(ctx, Wo, bo, tmp, M, CD, CD);
    add_ln_kernel<<<M / 8, blk>>>(x1, tmp, g1, be1, o1);

    // FFN
    gemm_tf32<1><<<dim3(CDFF / 64, M / 128), blk>>>(o1, W1, b1, hid, M, CDFF, CD);
    gemm_tf32<0><<<dim3(CD / 64, M / 128), blk>>>(hid, W2, b2, tmp, M, CD, CDFF);
    add_ln_kernel<<<M / 8, blk>>>(o1, tmp, g2, be2, out);
}

// round 2
// speedup vs baseline: 1.1576x; 1.1576x over previous
#include <cuda_runtime.h>
#include <mma.h>

using namespace nvcuda;

#define CB   128
#define CN1  256
#define CN2  256
#define CD   256
#define CH   8
#define CDH  32
#define CDFF 1024

// ---------------- scratch (device globals) ----------------
__device__ float g_wqkv[CD * 768];
__device__ float g_bqkv[768];
__device__ float g_wkv [CD * 512];
__device__ float g_bkv [512];
__device__ float g_qkv [CB * CN1 * 768];
__device__ float g_kv2 [CB * CN2 * 512];
__device__ float g_ctx [CB * CN1 * CD];
__device__ float g_tmp [CB * CN1 * CD];
__device__ float g_o1  [CB * CN1 * CD];
__device__ float g_hid [CB * CN1 * CDFF];

typedef wmma::fragment<wmma::matrix_a, 16, 16, 8, wmma::precision::tf32, wmma::row_major> AFrag;
typedef wmma::fragment<wmma::matrix_b, 16, 16, 8, wmma::precision::tf32, wmma::row_major> BFragR;
typedef wmma::fragment<wmma::matrix_b, 16, 16, 8, wmma::precision::tf32, wmma::col_major> BFragC;
typedef wmma::fragment<wmma::accumulator, 16, 16, 8, float> CFrag;

// ---------------- cp.async helpers ----------------
__device__ __forceinline__ void cp16(float* s, const float* g) {
    unsigned sa = (unsigned)__cvta_generic_to_shared(s);
    asm volatile("cp.async.cg.shared.global [%0], [%1], 16;\n" :: "r"(sa), "l"(g));
}
__device__ __forceinline__ void cp_commit() { asm volatile("cp.async.commit_group;\n"); }
template <int N> __device__ __forceinline__ void cp_wait() {
    asm volatile("cp.async.wait_group %0;\n" :: "n"(N));
}

// ============================================================================
// Pipelined tf32 GEMM: C[M,N] = A[M,K] @ W[K,N] + bias  (EPI==1: ReLU)
// 128x128x32 block tile, 3-stage cp.async pipeline, 8 warps (4m x 2n),
// warp tile 32x64 (2x4 wmma). No explicit tf32 rounding (HW truncation).
// ============================================================================
#define BM 128
#define BN 128
#define BK 32
#define ASTR 36
#define BSTR 132
#define STAGE_FLOATS (BM * ASTR + BK * BSTR)     // 8832
#define GSMEM_BYTES  (3 * STAGE_FLOATS * 4)      // 105984

template <int EPI>
__global__ __launch_bounds__(256, 2)
void gemm_tf32(const float* __restrict__ A, const float* __restrict__ W,
               const float* __restrict__ bias, float* __restrict__ C,
               int M, int N, int K)
{
    extern __shared__ float sm[];
    const int tid  = threadIdx.x;
    const int warp = tid >> 5;
    const int wm   = warp & 3;      // rows: wm*32
    const int wn   = warp >> 2;     // cols: wn*64
    const int m0   = blockIdx.y * BM;
    const int n0   = blockIdx.x * BN;
    const int kt   = K / BK;

    auto loadStage = [&](int t) {
        float* As = sm + (t % 3) * STAGE_FLOATS;
        float* Ws = As + BM * ASTR;
        const int k0 = t * BK;
#pragma unroll
        for (int j = 0; j < 4; j++) {
            int i = tid + j * 256;
            int r = i >> 3, c4 = i & 7;
            cp16(As + r * ASTR + c4 * 4, A + (size_t)(m0 + r) * K + k0 + c4 * 4);
        }
#pragma unroll
        for (int j = 0; j < 4; j++) {
            int i = tid + j * 256;
            int r = i >> 5, c4 = i & 31;
            cp16(Ws + r * BSTR + c4 * 4, W + (size_t)(k0 + r) * N + n0 + c4 * 4);
        }
        cp_commit();
    };

    CFrag acc[2][4];
#pragma unroll
    for (int i = 0; i < 2; i++)
#pragma unroll
        for (int j = 0; j < 4; j++) wmma::fill_fragment(acc[i][j], 0.0f);

    loadStage(0);
    if (kt > 1) loadStage(1);

    for (int t = 0; t < kt; t++) {
        if (t + 1 < kt) cp_wait<1>(); else cp_wait<0>();
        __syncthreads();
        if (t + 2 < kt) loadStage(t + 2);

        const float* As = sm + (t % 3) * STAGE_FLOATS;
        const float* Ws = As + BM * ASTR;
#pragma unroll
        for (int kk = 0; kk < BK; kk += 8) {
            AFrag  a[2];
            BFragR b[4];
#pragma unroll
            for (int i = 0; i < 2; i++)
                wmma::load_matrix_sync(a[i], As + (wm * 32 + i * 16) * ASTR + kk, ASTR);
#pragma unroll
            for (int j = 0; j < 4; j++)
                wmma::load_matrix_sync(b[j], Ws + kk * BSTR + wn * 64 + j * 16, BSTR);
#pragma unroll
            for (int i = 0; i < 2; i++)
#pragma unroll
                for (int j = 0; j < 4; j++)
                    wmma::mma_sync(acc[i][j], a[i], b[j], acc[i][j]);
        }
        __syncthreads();
    }

    // epilogue through smem stage
    float* stage = sm;
#pragma unroll
    for (int i = 0; i < 2; i++)
#pragma unroll
        for (int j = 0; j < 4; j++)
            wmma::store_matrix_sync(stage + (wm * 32 + i * 16) * BSTR + wn * 64 + j * 16,
                                    acc[i][j], BSTR, wmma::mem_row_major);
    __syncthreads();

#pragma unroll
    for (int j = 0; j < 16; j++) {
        int i = tid + j * 256;          // 4096 float4 slots (128 x 32)
        int r = i >> 5, c4 = (i & 31) * 4;
        float4 v = *(const float4*)(stage + r * BSTR + c4);
        const float* bp = bias + n0 + c4;
        v.x += bp[0]; v.y += bp[1]; v.z += bp[2]; v.w += bp[3];
        if (EPI == 1) {
            v.x = fmaxf(v.x, 0.f); v.y = fmaxf(v.y, 0.f);
            v.z = fmaxf(v.z, 0.f); v.w = fmaxf(v.w, 0.f);
        }
        *(float4*)(C + (size_t)(m0 + r) * N + n0 + c4) = v;
    }
}

// ============================================================================
// Fused dual-source graph attention. Grid (N1/128, H, B), 512 threads.
// 128 query rows per block, K/V tiles of 256x32, padded smem, dual-chain PV.
// ============================================================================
#define QSTR 36
#define SSTR 260
#define ATT_SMEM_FLOATS (128 * QSTR + 256 * QSTR + 256 * QSTR + 128 * SSTR)
#define ATT_SMEM_BYTES  (ATT_SMEM_FLOATS * 4)    // 225280

__global__ __launch_bounds__(512, 1)
void attn_kernel(const float* __restrict__ qkv, const float* __restrict__ kv2,
                 const float* __restrict__ adj1, const float* __restrict__ mask1,
                 const float* __restrict__ mask2, float* __restrict__ ctx)
{
    extern __shared__ float sm[];
    float* sQ = sm;                    // [128][36]
    float* sK = sQ + 128 * QSTR;       // [256][36]
    float* sV = sK + 256 * QSTR;       // [256][36]
    float* sS = sV + 256 * QSTR;       // [128][260]

    const int b  = blockIdx.z;
    const int h  = blockIdx.y;
    const int q0 = blockIdx.x * 128;
    const int tid  = threadIdx.x;
    const int warp = tid >> 5;
    const float scale = 0.17677669529663687f;    // 1/sqrt(32)

    // Q tile: 128x32
#pragma unroll
    for (int j = 0; j < 2; j++) {
        int i = tid + j * 512;
        int r = i >> 3, c4 = i & 7;
        float4 v = *(const float4*)(qkv + (size_t)(b * CN1 + q0 + r) * 768 + h * CDH + c4 * 4);
        float* d = sQ + r * QSTR + c4 * 4;
        d[0] = v.x; d[1] = v.y; d[2] = v.z; d[3] = v.w;
    }

    const int rt = warp >> 1;    // 0..7: rows rt*16
    const int ct = warp & 1;     // 0..1: cols ct*16
    CFrag acc0, acc1;
    wmma::fill_fragment(acc0, 0.0f);
    wmma::fill_fragment(acc1, 0.0f);

#pragma unroll 1
    for (int src = 0; src < 2; src++) {
        const float* base = src ? kv2 : qkv;
        const int stride  = src ? 512 : 768;
        const int koff    = src ? 0   : 256;
        const int voff    = src ? 256 : 512;

        // K,V tiles: 256x32 each
#pragma unroll
        for (int j = 0; j < 4; j++) {
            int i = tid + j * 512;
            int r = i >> 3, c4 = i & 7;
            const float* row = base + (size_t)(b * 256 + r) * stride + h * CDH + c4 * 4;
            float4 kv = *(const float4*)(row + koff);
            float4 vv = *(const float4*)(row + voff);
            float* dk = sK + r * QSTR + c4 * 4;
            float* dv = sV + r * QSTR + c4 * 4;
            dk[0] = kv.x; dk[1] = kv.y; dk[2] = kv.z; dk[3] = kv.w;
            dv[0] = vv.x; dv[1] = vv.y; dv[2] = vv.z; dv[3] = vv.w;
        }
        __syncthreads();

        // S = Q @ K^T  (128x256): warp -> rows (warp>>1)*16, col half (warp&1)*128
        {
            const int sr = (warp >> 1) * 16;
            const int cb = (warp & 1) * 128;
            CFrag accs[8];
#pragma unroll
            for (int c = 0; c < 8; c++) wmma::fill_fragment(accs[c], 0.0f);
#pragma unroll
            for (int kk = 0; kk < 32; kk += 8) {
                AFrag a;
                wmma::load_matrix_sync(a, sQ + sr * QSTR + kk, QSTR);
#pragma unroll
                for (int c = 0; c < 8; c++) {
                    BFragC bf;
                    wmma::load_matrix_sync(bf, sK + (cb + c * 16) * QSTR + kk, QSTR);
                    wmma::mma_sync(accs[c], a, bf, accs[c]);
                }
            }
#pragma unroll
            for (int c = 0; c < 8; c++)
                wmma::store_matrix_sync(sS + sr * SSTR + cb + c * 16, accs[c],
                                        SSTR, wmma::mem_row_major);
        }
        __syncthreads();

        // masked softmax: 4 threads/row, 64 cols each
        {
            const int r  = tid >> 2;
            const int qd = tid & 3;
            float* srow = sS + r * SSTR + qd * 64;
            float mx = -1e30f;
            if (src == 0) {
                const float* adjrow = adj1 + ((size_t)b * CN1 + q0 + r) * CN1 + qd * 64;
                const float* m1row  = mask1 + (size_t)b * CN1 + qd * 64;
#pragma unroll 8
                for (int j = 0; j < 64; j++) {
                    float s = srow[j] * scale;
                    float m = adjrow[j] * m1row[j];
                    s = (m > 0.0f) ? s : -1e9f;
                    srow[j] = s;
                    mx = fmaxf(mx, s);
                }
            } else {
                const float* m2row = mask2 + (size_t)b * CN2 + qd * 64;
#pragma unroll 8
                for (int j = 0; j < 64; j++) {
                    float s = srow[j] * scale;
                    s = (m2row[j] > 0.0f) ? s : -1e9f;
                    srow[j] = s;
                    mx = fmaxf(mx, s);
                }
            }
            mx = fmaxf(mx, __shfl_xor_sync(0xffffffffu, mx, 1));
            mx = fmaxf(mx, __shfl_xor_sync(0xffffffffu, mx, 2));
            float sum = 0.0f;
#pragma unroll 8
            for (int j = 0; j < 64; j++) {
                float e = __expf(srow[j] - mx);
                srow[j] = e;
                sum += e;
            }
            sum += __shfl_xor_sync(0xffffffffu, sum, 1);
            sum += __shfl_xor_sync(0xffffffffu, sum, 2);
            float inv = 1.0f / sum;
#pragma unroll 8
            for (int j = 0; j < 64; j++) srow[j] *= inv;
        }
        __syncthreads();

        // ctx += P @ V : two independent accumulation chains
#pragma unroll
        for (int kk = 0; kk < 256; kk += 16) {
            AFrag a0, a1;
            BFragR b0, b1;
            wmma::load_matrix_sync(a0, sS + (rt * 16) * SSTR + kk, SSTR);
            wmma::load_matrix_sync(a1, sS + (rt * 16) * SSTR + kk + 8, SSTR);
            wmma::load_matrix_sync(b0, sV + kk * QSTR + ct * 16, QSTR);
            wmma::load_matrix_sync(b1, sV + (kk + 8) * QSTR + ct * 16, QSTR);
            wmma::mma_sync(acc0, a0, b0, acc0);
            wmma::mma_sync(acc1, a1, b1, acc1);
        }
        __syncthreads();
    }

#pragma unroll
    for (int i = 0; i < acc0.num_elements; i++) acc0.x[i] += acc1.x[i];
    float* out = ctx + ((size_t)(b * CN1 + q0 + rt * 16) * CD + h * CDH + ct * 16);
    wmma::store_matrix_sync(out, acc0, CD, wmma::mem_row_major);
}

// ============================================================================
// out = LayerNorm(X + Y) * g + be   (row 256, one warp per row)
// ============================================================================
__global__ __launch_bounds__(256)
void add_ln_kernel(const float* __restrict__ X, const float* __restrict__ Y,
                   const float* __restrict__ g, const float* __restrict__ be,
                   float* __restrict__ out)
{
    const int warp = threadIdx.x >> 5;
    const int lane = threadIdx.x & 31;
    const size_t row = (size_t)blockIdx.x * 8 + warp;
    const float* x = X + row * CD;
    const float* y = Y + row * CD;

    float v[8];
    float s = 0.0f;
#pragma unroll
    for (int i = 0; i < 8; i++) { v[i] = x[lane + i * 32] + y[lane + i * 32]; s += v[i]; }
#pragma unroll
    for (int o = 16; o > 0; o >>= 1) s += __shfl_xor_sync(0xffffffffu, s, o);
    const float mu = s * (1.0f / CD);
    float s2 = 0.0f;
#pragma unroll
    for (int i = 0; i < 8; i++) { float d = v[i] - mu; s2 += d * d; }
#pragma unroll
    for (int o = 16; o > 0; o >>= 1) s2 += __shfl_xor_sync(0xffffffffu, s2, o);
    const float inv = rsqrtf(s2 * (1.0f / CD) + 1e-6f);
#pragma unroll
    for (int i = 0; i < 8; i++) {
        int c = lane + i * 32;
        out[row * CD + c] = g[c] * (v[i] - mu) * inv + be[c];
    }
}

// ---------------- weight packing ----------------
__global__ void pack_qkv(const float* __restrict__ Wq, const float* __restrict__ Wk,
                         const float* __restrict__ Wv, const float* __restrict__ bq,
                         const float* __restrict__ bk, const float* __restrict__ bv,
                         float* __restrict__ Wc, float* __restrict__ bc)
{
    int i = blockIdx.x * 256 + threadIdx.x;     // 65536 threads
    int r = i >> 8, c = i & 255;
    Wc[r * 768 + c]       = Wq[i];
    Wc[r * 768 + 256 + c] = Wk[i];
    Wc[r * 768 + 512 + c] = Wv[i];
    if (i < 256) { bc[i] = bq[i]; bc[256 + i] = bk[i]; bc[512 + i] = bv[i]; }
}

__global__ void pack_kv(const float* __restrict__ Wk, const float* __restrict__ Wv,
                        const float* __restrict__ bk, const float* __restrict__ bv,
                        float* __restrict__ Wc, float* __restrict__ bc)
{
    int i = blockIdx.x * 256 + threadIdx.x;
    int r = i >> 8, c = i & 255;
    Wc[r * 512 + c]       = Wk[i];
    Wc[r * 512 + 256 + c] = Wv[i];
    if (i < 256) { bc[i] = bk[i]; bc[256 + i] = bv[i]; }
}

// ============================================================================
// Host launch
// ============================================================================
extern "C" void kernel_launch(void* const* d_in, const int* in_sizes, int n_in,
                              void* d_out, int out_size)
{
    const float* x1    = (const float*)d_in[0];
    const float* adj1  = (const float*)d_in[1];
    const float* mask1 = (const float*)d_in[2];
    const float* x2    = (const float*)d_in[3];
    const float* mask2 = (const float*)d_in[4];
    const float* Wq = (const float*)d_in[5];  const float* bq = (const float*)d_in[6];
    const float* Wk = (const float*)d_in[7];  const float* bk = (const float*)d_in[8];
    const float* Wv = (const float*)d_in[9];  const float* bv = (const float*)d_in[10];
    const float* Wo = (const float*)d_in[11]; const float* bo = (const float*)d_in[12];
    const float* W1 = (const float*)d_in[13]; const float* b1 = (const float*)d_in[14];
    const float* W2 = (const float*)d_in[15]; const float* b2 = (const float*)d_in[16];
    const float* g1 = (const float*)d_in[17]; const float* be1 = (const float*)d_in[18];
    const float* g2 = (const float*)d_in[19]; const float* be2 = (const float*)d_in[20];
    float* out = (float*)d_out;

    float *wqkv, *bqkv, *wkv, *bkv, *qkv, *kv2, *ctx, *tmp, *o1, *hid;
    cudaGetSymbolAddress((void**)&wqkv, g_wqkv);
    cudaGetSymbolAddress((void**)&bqkv, g_bqkv);
    cudaGetSymbolAddress((void**)&wkv,  g_wkv);
    cudaGetSymbolAddress((void**)&bkv,  g_bkv);
    cudaGetSymbolAddress((void**)&qkv,  g_qkv);
    cudaGetSymbolAddress((void**)&kv2,  g_kv2);
    cudaGetSymbolAddress((void**)&ctx,  g_ctx);
    cudaGetSymbolAddress((void**)&tmp,  g_tmp);
    cudaGetSymbolAddress((void**)&o1,   g_o1);
    cudaGetSymbolAddress((void**)&hid,  g_hid);

    cudaFuncSetAttribute(gemm_tf32<0>, cudaFuncAttributeMaxDynamicSharedMemorySize, GSMEM_BYTES);
    cudaFuncSetAttribute(gemm_tf32<1>, cudaFuncAttributeMaxDynamicSharedMemorySize, GSMEM_BYTES);
    cudaFuncSetAttribute(attn_kernel,  cudaFuncAttributeMaxDynamicSharedMemorySize, ATT_SMEM_BYTES);

    const int M = CB * CN1;          // 32768
    dim3 blk(256);

    // pack weights, fused projections
    pack_qkv<<<256, blk>>>(Wq, Wk, Wv, bq, bk, bv, wqkv, bqkv);
    pack_kv <<<256, blk>>>(Wk, Wv, bk, bv, wkv, bkv);
    gemm_tf32<0><<<dim3(768 / BN, M / BM), blk, GSMEM_BYTES>>>(x1, wqkv, bqkv, qkv, M, 768, CD);
    gemm_tf32<0><<<dim3(512 / BN, M / BM), blk, GSMEM_BYTES>>>(x2, wkv,  bkv,  kv2, M, 512, CD);

    // fused dual-source attention -> ctx
    attn_kernel<<<dim3(CN1 / 128, CH, CB), dim3(512), ATT_SMEM_BYTES>>>(
        qkv, kv2, adj1, mask1, mask2, ctx);

    // output projection + residual LN
    gemm_tf32<0><<<dim3(CD / BN, M / BM), blk, GSMEM_BYTES>>>(ctx, Wo, bo, tmp, M, CD, CD);
    add_ln_kernel<<<M / 8, blk>>>(x1, tmp, g1, be1, o1);

    // FFN
    gemm_tf32<1><<<dim3(CDFF / BN, M / BM), blk, GSMEM_BYTES>>>(o1, W1, b1, hid, M, CDFF, CD);
    gemm_tf32<0><<<dim3(CD / BN, M / BM), blk, GSMEM_BYTES>>>(hid, W2, b2, tmp, M, CD, CDFF);
    add_ln_kernel<<<M / 8, blk>>>(o1, tmp, g2, be2, out);
}

// round 4
// speedup vs baseline: 1.9982x; 1.7262x over previous
#include <cuda_runtime.h>
#include <mma.h>
#include <cstdint>

using namespace nvcuda;

#define CB   128
#define CN1  256
#define CN2  256
#define CD   256
#define CH   8
#define CDH  32
#define CDFF 1024

// ---------------- scratch (device globals) ----------------
__device__ float g_wqkv[CD * 768];
__device__ float g_bqkv[768];
__device__ float g_wkv [CD * 512];
__device__ float g_bkv [512];
__device__ float g_qkv [CB * CN1 * 768];
__device__ float g_kv2 [CB * CN2 * 512];
__device__ float g_ctx [CB * CN1 * CD];
__device__ float g_tmp [CB * CN1 * CD];
__device__ float g_o1  [CB * CN1 * CD];
__device__ float g_hid [CB * CN1 * CDFF];
__device__ uint32_t g_bm1[CB * CN1 * 8];   // adj1*mask1 > 0 bitmask
__device__ uint32_t g_bm2[CB * 8];         // mask2 > 0 bitmask

typedef wmma::fragment<wmma::matrix_a, 16, 16, 8, wmma::precision::tf32, wmma::row_major> AFrag;
typedef wmma::fragment<wmma::matrix_b, 16, 16, 8, wmma::precision::tf32, wmma::row_major> BFragR;
typedef wmma::fragment<wmma::accumulator, 16, 16, 8, float> CFrag;

// ---------------- cp.async helpers ----------------
__device__ __forceinline__ void cp16(float* s, const float* g) {
    unsigned sa = (unsigned)__cvta_generic_to_shared(s);
    asm volatile("cp.async.cg.shared.global [%0], [%1], 16;\n" :: "r"(sa), "l"(g));
}
__device__ __forceinline__ void cp_commit() { asm volatile("cp.async.commit_group;\n"); }
template <int N> __device__ __forceinline__ void cp_wait() {
    asm volatile("cp.async.wait_group %0;\n" :: "n"(N));
}

// raw tf32 mma m16n8k8 (row.col), fp32 accumulate
__device__ __forceinline__ void mma168(float* d, const uint32_t* a, const uint32_t* b) {
    asm volatile(
        "mma.sync.aligned.m16n8k8.row.col.f32.tf32.tf32.f32 "
        "{%0,%1,%2,%3}, {%4,%5,%6,%7}, {%8,%9}, {%0,%1,%2,%3};"
        : "+f"(d[0]), "+f"(d[1]), "+f"(d[2]), "+f"(d[3])
        : "r"(a[0]), "r"(a[1]), "r"(a[2]), "r"(a[3]), "r"(b[0]), "r"(b[1]));
}

// ============================================================================
// Pipelined tf32 GEMM (unchanged from R2): C = A @ W + bias (EPI==1: ReLU)
// ============================================================================
#define BM 128
#define BN 128
#define BK 32
#define ASTR 36
#define BSTR 132
#define STAGE_FLOATS (BM * ASTR + BK * BSTR)
#define GSMEM_BYTES  (3 * STAGE_FLOATS * 4)

template <int EPI>
__global__ __launch_bounds__(256, 2)
void gemm_tf32(const float* __restrict__ A, const float* __restrict__ W,
               const float* __restrict__ bias, float* __restrict__ C,
               int M, int N, int K)
{
    extern __shared__ float sm[];
    const int tid  = threadIdx.x;
    const int warp = tid >> 5;
    const int wm   = warp & 3;
    const int wn   = warp >> 2;
    const int m0   = blockIdx.y * BM;
    const int n0   = blockIdx.x * BN;
    const int kt   = K / BK;

    auto loadStage = [&](int t) {
        float* As = sm + (t % 3) * STAGE_FLOATS;
        float* Ws = As + BM * ASTR;
        const int k0 = t * BK;
#pragma unroll
        for (int j = 0; j < 4; j++) {
            int i = tid + j * 256;
            int r = i >> 3, c4 = i & 7;
            cp16(As + r * ASTR + c4 * 4, A + (size_t)(m0 + r) * K + k0 + c4 * 4);
        }
#pragma unroll
        for (int j = 0; j < 4; j++) {
            int i = tid + j * 256;
            int r = i >> 5, c4 = i & 31;
            cp16(Ws + r * BSTR + c4 * 4, W + (size_t)(k0 + r) * N + n0 + c4 * 4);
        }
        cp_commit();
    };

    CFrag acc[2][4];
#pragma unroll
    for (int i = 0; i < 2; i++)
#pragma unroll
        for (int j = 0; j < 4; j++) wmma::fill_fragment(acc[i][j], 0.0f);

    loadStage(0);
    if (kt > 1) loadStage(1);

    for (int t = 0; t < kt; t++) {
        if (t + 1 < kt) cp_wait<1>(); else cp_wait<0>();
        __syncthreads();
        if (t + 2 < kt) loadStage(t + 2);

        const float* As = sm + (t % 3) * STAGE_FLOATS;
        const float* Ws = As + BM * ASTR;
#pragma unroll
        for (int kk = 0; kk < BK; kk += 8) {
            AFrag  a[2];
            BFragR b[4];
#pragma unroll
            for (int i = 0; i < 2; i++)
                wmma::load_matrix_sync(a[i], As + (wm * 32 + i * 16) * ASTR + kk, ASTR);
#pragma unroll
            for (int j = 0; j < 4; j++)
                wmma::load_matrix_sync(b[j], Ws + kk * BSTR + wn * 64 + j * 16, BSTR);
#pragma unroll
            for (int i = 0; i < 2; i++)
#pragma unroll
                for (int j = 0; j < 4; j++)
                    wmma::mma_sync(acc[i][j], a[i], b[j], acc[i][j]);
        }
        __syncthreads();
    }

    float* stage = sm;
#pragma unroll
    for (int i = 0; i < 2; i++)
#pragma unroll
        for (int j = 0; j < 4; j++)
            wmma::store_matrix_sync(stage + (wm * 32 + i * 16) * BSTR + wn * 64 + j * 16,
                                    acc[i][j], BSTR, wmma::mem_row_major);
    __syncthreads();

#pragma unroll
    for (int j = 0; j < 16; j++) {
        int i = tid + j * 256;
        int r = i >> 5, c4 = (i & 31) * 4;
        float4 v = *(const float4*)(stage + r * BSTR + c4);
        const float* bp = bias + n0 + c4;
        v.x += bp[0]; v.y += bp[1]; v.z += bp[2]; v.w += bp[3];
        if (EPI == 1) {
            v.x = fmaxf(v.x, 0.f); v.y = fmaxf(v.y, 0.f);
            v.z = fmaxf(v.z, 0.f); v.w = fmaxf(v.w, 0.f);
        }
        *(float4*)(C + (size_t)(m0 + r) * N + n0 + c4) = v;
    }
}

// ============================================================================
// FlashAttention-style dual-source graph attention.
// Grid (N1/128, H, B), 256 threads (8 warps), 16 q-rows per warp.
// S in registers; online masked softmax; P->A via quad shuffles.
// ============================================================================
#define KVSTR 36
#define ATT_F   (2 * 256 * KVSTR)                 // sK + sV floats
#define ATT_BM_OFF (ATT_F * 4)                    // byte offset of bitmask area
#define ATT_SMEM_BYTES (ATT_BM_OFF + (1024 + 8) * 4)

__global__ __launch_bounds__(256, 2)
void attn_kernel(const float* __restrict__ qkv, const float* __restrict__ kv2,
                 const uint32_t* __restrict__ bm1, const uint32_t* __restrict__ bm2,
                 float* __restrict__ ctx)
{
    extern __shared__ float sm[];
    float* sK = sm;                                // [256][36]
    float* sV = sK + 256 * KVSTR;                  // [256][36]
    uint32_t* sBM  = (uint32_t*)((char*)sm + ATT_BM_OFF);   // [128][8]
    uint32_t* sBM2 = sBM + 1024;                   // [8]

    const int b  = blockIdx.z;
    const int h  = blockIdx.y;
    const int q0 = blockIdx.x * 128;
    const int tid  = threadIdx.x;
    const int warp = tid >> 5;
    const int lane = tid & 31;
    const int qr   = lane >> 2;          // row within 16 (and +8)
    const int qc   = lane & 3;           // col quad index
    const float scale = 0.17677669529663687f;

    // bitmasks -> smem
#pragma unroll
    for (int j = 0; j < 4; j++) {
        int i = tid + j * 256;
        sBM[i] = bm1[((size_t)(b * CN1) + q0 + (i >> 3)) * 8 + (i & 7)];
    }
    if (tid < 8) sBM2[tid] = bm2[b * 8 + tid];

    // Q fragments (scale folded in): rows q0 + warp*16 + qr(+8), cols kf*8 + qc(+4)
    uint32_t qf[4][4];
    {
        const float* Qb = qkv + (size_t)(b * CN1 + q0 + warp * 16) * 768 + h * CDH;
#pragma unroll
        for (int kf = 0; kf < 4; kf++) {
            qf[kf][0] = __float_as_uint(Qb[(size_t)qr * 768 + kf * 8 + qc] * scale);
            qf[kf][1] = __float_as_uint(Qb[(size_t)(qr + 8) * 768 + kf * 8 + qc] * scale);
            qf[kf][2] = __float_as_uint(Qb[(size_t)qr * 768 + kf * 8 + qc + 4] * scale);
            qf[kf][3] = __float_as_uint(Qb[(size_t)(qr + 8) * 768 + kf * 8 + qc + 4] * scale);
        }
    }

    float ofin[4][4];
#pragma unroll
    for (int n = 0; n < 4; n++)
#pragma unroll
        for (int e = 0; e < 4; e++) ofin[n][e] = 0.0f;

#pragma unroll 1
    for (int src = 0; src < 2; src++) {
        const float* base = src ? kv2 : qkv;
        const int stride  = src ? 512 : 768;
        const int koff    = src ? 0   : 256;
        const int voff    = src ? 256 : 512;

        __syncthreads();   // protect smem reuse from previous source
#pragma unroll
        for (int j = 0; j < 8; j++) {
            int i = tid + j * 256;
            int r = i >> 3, c4 = i & 7;
            const float* row = base + (size_t)(b * 256 + r) * stride + h * CDH + c4 * 4;
            *(float4*)(sK + r * KVSTR + c4 * 4) = *(const float4*)(row + koff);
            *(float4*)(sV + r * KVSTR + c4 * 4) = *(const float4*)(row + voff);
        }
        __syncthreads();

        float m0 = -1e30f, m1 = -1e30f, l0 = 0.0f, l1 = 0.0f;
        float o[4][4];
#pragma unroll
        for (int n = 0; n < 4; n++)
#pragma unroll
            for (int e = 0; e < 4; e++) o[n][e] = 0.0f;

#pragma unroll 1
        for (int chunk = 0; chunk < 4; chunk++) {
            const int key0 = chunk * 64;

            // ---- S = Q @ K^T for 8 n-frags ----
            float s[8][4];
#pragma unroll
            for (int nf = 0; nf < 8; nf++) {
                s[nf][0] = s[nf][1] = s[nf][2] = s[nf][3] = 0.0f;
                const float* kb = sK + (size_t)(key0 + nf * 8 + qr) * KVSTR;
#pragma unroll
                for (int kf = 0; kf < 4; kf++) {
                    uint32_t bfr[2];
                    bfr[0] = __float_as_uint(kb[kf * 8 + qc]);
                    bfr[1] = __float_as_uint(kb[kf * 8 + qc + 4]);
                    mma168(s[nf], qf[kf], bfr);
                }
            }

            // ---- mask + chunk max ----
            uint32_t wa0, wa1, wb0, wb1;
            if (src == 0) {
                const uint32_t* ra = sBM + (warp * 16 + qr) * 8 + chunk * 2;
                const uint32_t* rb = sBM + (warp * 16 + qr + 8) * 8 + chunk * 2;
                wa0 = ra[0]; wa1 = ra[1]; wb0 = rb[0]; wb1 = rb[1];
            } else {
                wa0 = sBM2[chunk * 2]; wa1 = sBM2[chunk * 2 + 1];
                wb0 = wa0; wb1 = wa1;
            }
            float cm0 = -1e30f, cm1 = -1e30f;
#pragma unroll
            for (int nf = 0; nf < 8; nf++) {
                const int sh = (nf & 3) * 8 + qc * 2;
                const uint32_t ba = ((nf < 4 ? wa0 : wa1) >> sh);
                const uint32_t bb = ((nf < 4 ? wb0 : wb1) >> sh);
                s[nf][0] = (ba & 1u) ? s[nf][0] : -1e9f;
                s[nf][1] = (ba & 2u) ? s[nf][1] : -1e9f;
                s[nf][2] = (bb & 1u) ? s[nf][2] : -1e9f;
                s[nf][3] = (bb & 2u) ? s[nf][3] : -1e9f;
                cm0 = fmaxf(cm0, fmaxf(s[nf][0], s[nf][1]));
                cm1 = fmaxf(cm1, fmaxf(s[nf][2], s[nf][3]));
            }
            cm0 = fmaxf(cm0, __shfl_xor_sync(0xffffffffu, cm0, 1));
            cm0 = fmaxf(cm0, __shfl_xor_sync(0xffffffffu, cm0, 2));
            cm1 = fmaxf(cm1, __shfl_xor_sync(0xffffffffu, cm1, 1));
            cm1 = fmaxf(cm1, __shfl_xor_sync(0xffffffffu, cm1, 2));

            const float mn0 = fmaxf(m0, cm0), mn1 = fmaxf(m1, cm1);
            const float f0 = __expf(m0 - mn0), f1 = __expf(m1 - mn1);
            m0 = mn0; m1 = mn1;
            l0 *= f0; l1 *= f1;
#pragma unroll
            for (int n = 0; n < 4; n++) {
                o[n][0] *= f0; o[n][1] *= f0;
                o[n][2] *= f1; o[n][3] *= f1;
            }

            // ---- P = exp(S - m), accumulate l ----
#pragma unroll
            for (int nf = 0; nf < 8; nf++) {
                s[nf][0] = __expf(s[nf][0] - mn0);
                s[nf][1] = __expf(s[nf][1] - mn0);
                s[nf][2] = __expf(s[nf][2] - mn1);
                s[nf][3] = __expf(s[nf][3] - mn1);
                l0 += s[nf][0] + s[nf][1];
                l1 += s[nf][2] + s[nf][3];
            }

            // ---- PV: convert P frag kfp -> A layout (quad shuffles), then mma ----
            const int srcA = (lane & ~3) | (qc >> 1);
            const int srcB = srcA + 2;
#pragma unroll
            for (int kfp = 0; kfp < 8; kfp++) {
                float v00 = __shfl_sync(0xffffffffu, s[kfp][0], srcA);
                float v01 = __shfl_sync(0xffffffffu, s[kfp][1], srcA);
                float v20 = __shfl_sync(0xffffffffu, s[kfp][2], srcA);
                float v21 = __shfl_sync(0xffffffffu, s[kfp][3], srcA);
                float v40 = __shfl_sync(0xffffffffu, s[kfp][0], srcB);
                float v41 = __shfl_sync(0xffffffffu, s[kfp][1], srcB);
                float v60 = __shfl_sync(0xffffffffu, s[kfp][2], srcB);
                float v61 = __shfl_sync(0xffffffffu, s[kfp][3], srcB);
                uint32_t af[4];
                af[0] = __float_as_uint((qc & 1) ? v01 : v00);
                af[1] = __float_as_uint((qc & 1) ? v21 : v20);
                af[2] = __float_as_uint((qc & 1) ? v41 : v40);
                af[3] = __float_as_uint((qc & 1) ? v61 : v60);

                const float* vb = sV + (size_t)(key0 + kfp * 8 + qc) * KVSTR;
                const float* vb4 = vb + 4 * KVSTR;
#pragma unroll
                for (int n = 0; n < 4; n++) {
                    uint32_t bfr[2];
                    bfr[0] = __float_as_uint(vb[n * 8 + (qc == qc ? (lane >> 2) : 0)]);
                    bfr[1] = __float_as_uint(vb4[n * 8 + (lane >> 2)]);
                    mma168(o[n], af, bfr);
                }
            }
        }

        // normalize this source and accumulate
        l0 += __shfl_xor_sync(0xffffffffu, l0, 1);
        l0 += __shfl_xor_sync(0xffffffffu, l0, 2);
        l1 += __shfl_xor_sync(0xffffffffu, l1, 1);
        l1 += __shfl_xor_sync(0xffffffffu, l1, 2);
        const float i0 = 1.0f / l0, i1 = 1.0f / l1;
#pragma unroll
        for (int n = 0; n < 4; n++) {
            ofin[n][0] += o[n][0] * i0;
            ofin[n][1] += o[n][1] * i0;
            ofin[n][2] += o[n][2] * i1;
            ofin[n][3] += o[n][3] * i1;
        }
    }

    // store ctx
    float* outA = ctx + (size_t)(b * CN1 + q0 + warp * 16 + qr) * CD + h * CDH + qc * 2;
    float* outB = outA + 8 * CD;
#pragma unroll
    for (int n = 0; n < 4; n++) {
        *(float2*)(outA + n * 8) = make_float2(ofin[n][0], ofin[n][1]);
        *(float2*)(outB + n * 8) = make_float2(ofin[n][2], ofin[n][3]);
    }
}

// ============================================================================
// out = LayerNorm(X + Y) * g + be
// ============================================================================
__global__ __launch_bounds__(256)
void add_ln_kernel(const float* __restrict__ X, const float* __restrict__ Y,
                   const float* __restrict__ g, const float* __restrict__ be,
                   float* __restrict__ out)
{
    const int warp = threadIdx.x >> 5;
    const int lane = threadIdx.x & 31;
    const size_t row = (size_t)blockIdx.x * 8 + warp;
    const float* x = X + row * CD;
    const float* y = Y + row * CD;
    float v[8];
    float s = 0.0f;
#pragma unroll
    for (int i = 0; i < 8; i++) { v[i] = x[lane + i * 32] + y[lane + i * 32]; s += v[i]; }
#pragma unroll
    for (int o = 16; o > 0; o >>= 1) s += __shfl_xor_sync(0xffffffffu, s, o);
    const float mu = s * (1.0f / CD);
    float s2 = 0.0f;
#pragma unroll
    for (int i = 0; i < 8; i++) { float d = v[i] - mu; s2 += d * d; }
#pragma unroll
    for (int o = 16; o > 0; o >>= 1) s2 += __shfl_xor_sync(0xffffffffu, s2, o);
    const float inv = rsqrtf(s2 * (1.0f / CD) + 1e-6f);
#pragma unroll
    for (int i = 0; i < 8; i++) {
        int c = lane + i * 32;
        out[row * CD + c] = g[c] * (v[i] - mu) * inv + be[c];
    }
}

// ---------------- weight packing + mask bitmaps ----------------
__global__ void pack_qkv(const float* __restrict__ Wq, const float* __restrict__ Wk,
                         const float* __restrict__ Wv, const float* __restrict__ bq,
                         const float* __restrict__ bk, const float* __restrict__ bv,
                         float* __restrict__ Wc, float* __restrict__ bc)
{
    int i = blockIdx.x * 256 + threadIdx.x;
    int r = i >> 8, c = i & 255;
    Wc[r * 768 + c]       = Wq[i];
    Wc[r * 768 + 256 + c] = Wk[i];
    Wc[r * 768 + 512 + c] = Wv[i];
    if (i < 256) { bc[i] = bq[i]; bc[256 + i] = bk[i]; bc[512 + i] = bv[i]; }
}

__global__ void pack_kv(const float* __restrict__ Wk, const float* __restrict__ Wv,
                        const float* __restrict__ bk, const float* __restrict__ bv,
                        float* __restrict__ Wc, float* __restrict__ bc)
{
    int i = blockIdx.x * 256 + threadIdx.x;
    int r = i >> 8, c = i & 255;
    Wc[r * 512 + c]       = Wk[i];
    Wc[r * 512 + 256 + c] = Wv[i];
    if (i < 256) { bc[i] = bk[i]; bc[256 + i] = bv[i]; }
}

__global__ void build_bm1(const float* __restrict__ adj, const float* __restrict__ mask1,
                          uint32_t* __restrict__ bm)
{
    const int gw = (blockIdx.x * blockDim.x + threadIdx.x) >> 5;
    const int lane = threadIdx.x & 31;
    const int b = gw >> 8;
    const float* arow = adj + (size_t)gw * 256;
    const float* m1 = mask1 + (size_t)b * 256;
#pragma unroll
    for (int w = 0; w < 8; w++) {
        float v = arow[w * 32 + lane] * m1[w * 32 + lane];
        uint32_t bits = __ballot_sync(0xffffffffu, v > 0.0f);
        if (lane == 0) bm[(size_t)gw * 8 + w] = bits;
    }
}

__global__ void build_bm2(const float* __restrict__ mask2, uint32_t* __restrict__ bm) {
    const int b = blockIdx.x;
    const int lane = threadIdx.x & 31;
    const int w = threadIdx.x >> 5;
    float v = mask2[(size_t)b * 256 + w * 32 + lane];
    uint32_t bits = __ballot_sync(0xffffffffu, v > 0.0f);
    if (lane == 0) bm[b * 8 + w] = bits;
}

// ============================================================================
// Host launch
// ============================================================================
extern "C" void kernel_launch(void* const* d_in, const int* in_sizes, int n_in,
                              void* d_out, int out_size)
{
    const float* x1    = (const float*)d_in[0];
    const float* adj1  = (const float*)d_in[1];
    const float* mask1 = (const float*)d_in[2];
    const float* x2    = (const float*)d_in[3];
    const float* mask2 = (const float*)d_in[4];
    const float* Wq = (const float*)d_in[5];  const float* bq = (const float*)d_in[6];
    const float* Wk = (const float*)d_in[7];  const float* bk = (const float*)d_in[8];
    const float* Wv = (const float*)d_in[9];  const float* bv = (const float*)d_in[10];
    const float* Wo = (const float*)d_in[11]; const float* bo = (const float*)d_in[12];
    const float* W1 = (const float*)d_in[13]; const float* b1 = (const float*)d_in[14];
    const float* W2 = (const float*)d_in[15]; const float* b2 = (const float*)d_in[16];
    const float* g1 = (const float*)d_in[17]; const float* be1 = (const float*)d_in[18];
    const float* g2 = (const float*)d_in[19]; const float* be2 = (const float*)d_in[20];
    float* out = (float*)d_out;

    float *wqkv, *bqkv, *wkv, *bkv, *qkv, *kv2, *ctx, *tmp, *o1, *hid;
    uint32_t *bm1, *bm2;
    cudaGetSymbolAddress((void**)&wqkv, g_wqkv);
    cudaGetSymbolAddress((void**)&bqkv, g_bqkv);
    cudaGetSymbolAddress((void**)&wkv,  g_wkv);
    cudaGetSymbolAddress((void**)&bkv,  g_bkv);
    cudaGetSymbolAddress((void**)&qkv,  g_qkv);
    cudaGetSymbolAddress((void**)&kv2,  g_kv2);
    cudaGetSymbolAddress((void**)&ctx,  g_ctx);
    cudaGetSymbolAddress((void**)&tmp,  g_tmp);
    cudaGetSymbolAddress((void**)&o1,   g_o1);
    cudaGetSymbolAddress((void**)&hid,  g_hid);
    cudaGetSymbolAddress((void**)&bm1,  g_bm1);
    cudaGetSymbolAddress((void**)&bm2,  g_bm2);

    cudaFuncSetAttribute(gemm_tf32<0>, cudaFuncAttributeMaxDynamicSharedMemorySize, GSMEM_BYTES);
    cudaFuncSetAttribute(gemm_tf32<1>, cudaFuncAttributeMaxDynamicSharedMemorySize, GSMEM_BYTES);
    cudaFuncSetAttribute(attn_kernel,  cudaFuncAttributeMaxDynamicSharedMemorySize, ATT_SMEM_BYTES);

    const int M = CB * CN1;
    dim3 blk(256);

    pack_qkv<<<256, blk>>>(Wq, Wk, Wv, bq, bk, bv, wqkv, bqkv);
    pack_kv <<<256, blk>>>(Wk, Wv, bk, bv, wkv, bkv);
    build_bm1<<<4096, blk>>>(adj1, mask1, bm1);
    build_bm2<<<CB, blk>>>(mask2, bm2);

    gemm_tf32<0><<<dim3(768 / BN, M / BM), blk, GSMEM_BYTES>>>(x1, wqkv, bqkv, qkv, M, 768, CD);
    gemm_tf32<0><<<dim3(512 / BN, M / BM), blk, GSMEM_BYTES>>>(x2, wkv,  bkv,  kv2, M, 512, CD);

    attn_kernel<<<dim3(CN1 / 128, CH, CB), blk, ATT_SMEM_BYTES>>>(qkv, kv2, bm1, bm2, ctx);

    gemm_tf32<0><<<dim3(CD / BN, M / BM), blk, GSMEM_BYTES>>>(ctx, Wo, bo, tmp, M, CD, CD);
    add_ln_kernel<<<M / 8, blk>>>(x1, tmp, g1, be1, o1);

    gemm_tf32<1><<<dim3(CDFF / BN, M / BM), blk, GSMEM_BYTES>>>(o1, W1, b1, hid, M, CDFF, CD);
    gemm_tf32<0><<<dim3(CD / BN, M / BM), blk, GSMEM_BYTES>>>(hid, W2, b2, tmp, M, CD, CDFF);
    add_ln_kernel<<<M / 8, blk>>>(o1, tmp, g2, be2, out);
}

// round 5
// speedup vs baseline: 3.5077x; 1.7554x over previous
#include <cuda_runtime.h>
#include <mma.h>
#include <cstdint>

#define CB   128
#define CN1  256
#define CN2  256
#define CD   256
#define CH   8
#define CDH  32
#define CDFF 1024

// ---------------- scratch (device globals) ----------------
__device__ float g_wqkv[CD * 768];
__device__ float g_bqkv[768];
__device__ float g_wkv [CD * 512];
__device__ float g_bkv [512];
__device__ float g_qkv [CB * CN1 * 768];
__device__ float g_kv2 [CB * CN2 * 512];
__device__ float g_ctx [CB * CN1 * CD];
__device__ float g_tmp [CB * CN1 * CD];
__device__ float g_o1  [CB * CN1 * CD];
__device__ float g_hid [CB * CN1 * CDFF];
__device__ uint32_t g_bm1[CB * CN1 * 8];
__device__ uint32_t g_bm2[CB * 8];

// ---------------- cp.async helpers ----------------
__device__ __forceinline__ void cp16(float* s, const float* g) {
    unsigned sa = (unsigned)__cvta_generic_to_shared(s);
    asm volatile("cp.async.cg.shared.global [%0], [%1], 16;\n" :: "r"(sa), "l"(g));
}
__device__ __forceinline__ void cp_commit() { asm volatile("cp.async.commit_group;\n"); }
template <int N> __device__ __forceinline__ void cp_wait() {
    asm volatile("cp.async.wait_group %0;\n" :: "n"(N));
}

// raw tf32 mma m16n8k8 (row.col), fp32 accumulate
__device__ __forceinline__ void mma168(float* d, const uint32_t* a, const uint32_t* b) {
    asm volatile(
        "mma.sync.aligned.m16n8k8.row.col.f32.tf32.tf32.f32 "
        "{%0,%1,%2,%3}, {%4,%5,%6,%7}, {%8,%9}, {%0,%1,%2,%3};"
        : "+f"(d[0]), "+f"(d[1]), "+f"(d[2]), "+f"(d[3])
        : "r"(a[0]), "r"(a[1]), "r"(a[2]), "r"(a[3]), "r"(b[0]), "r"(b[1]));
}

// ============================================================================
// tf32 GEMM, CUTLASS-style: block 128x128x32, 4 warps, warp tile 64x64,
// raw m16n8k8, 3-stage cp.async, register->global epilogue.
// ============================================================================
#define BM 128
#define BN 128
#define BK 32
#define ASTR 36
#define BSTR 136
#define STG (BM * ASTR + BK * BSTR)      // 8960 floats
#define GSMEM_BYTES (3 * STG * 4)        // 107520

template <int EPI>
__global__ __launch_bounds__(128, 2)
void gemm_tf32(const float* __restrict__ A, const float* __restrict__ W,
               const float* __restrict__ bias, float* __restrict__ C,
               int M, int N, int K)
{
    extern __shared__ float sm[];
    const int tid  = threadIdx.x;
    const int warp = tid >> 5;
    const int lane = tid & 31;
    const int wm   = warp & 1;           // row half: wm*64
    const int wn   = warp >> 1;          // col half: wn*64
    const int m0   = blockIdx.y * BM;
    const int n0   = blockIdx.x * BN;
    const int kt   = K / BK;
    const int qr   = lane >> 2;
    const int qc   = lane & 3;

    auto loadStage = [&](int t) {
        float* As = sm + (t % 3) * STG;
        float* Ws = As + BM * ASTR;
        const int k0 = t * BK;
#pragma unroll
        for (int j = 0; j < 8; j++) {
            int i = tid + j * 128;
            int r = i >> 3, c4 = i & 7;
            cp16(As + r * ASTR + c4 * 4, A + (size_t)(m0 + r) * K + k0 + c4 * 4);
        }
#pragma unroll
        for (int j = 0; j < 8; j++) {
            int i = tid + j * 128;
            int r = i >> 5, c4 = i & 31;
            cp16(Ws + r * BSTR + c4 * 4, W + (size_t)(k0 + r) * N + n0 + c4 * 4);
        }
        cp_commit();
    };

    float acc[4][8][4];
#pragma unroll
    for (int mt = 0; mt < 4; mt++)
#pragma unroll
        for (int nt = 0; nt < 8; nt++)
#pragma unroll
            for (int e = 0; e < 4; e++) acc[mt][nt][e] = 0.0f;

    loadStage(0);
    loadStage(1);

    for (int t = 0; t < kt; t++) {
        if (t + 1 < kt) cp_wait<1>(); else cp_wait<0>();
        __syncthreads();
        if (t + 2 < kt) loadStage(t + 2);

        const float* As = sm + (t % 3) * STG + (wm * 64) * ASTR;
        const float* Ws = sm + (t % 3) * STG + BM * ASTR + wn * 64;
#pragma unroll
        for (int kk = 0; kk < BK; kk += 8) {
            uint32_t af[4][4];
            uint32_t bf[8][2];
#pragma unroll
            for (int mt = 0; mt < 4; mt++) {
                const float* ab = As + (mt * 16 + qr) * ASTR + kk + qc;
                af[mt][0] = __float_as_uint(ab[0]);
                af[mt][1] = __float_as_uint(ab[8 * ASTR]);
                af[mt][2] = __float_as_uint(ab[4]);
                af[mt][3] = __float_as_uint(ab[8 * ASTR + 4]);
            }
#pragma unroll
            for (int nt = 0; nt < 8; nt++) {
                const float* bb = Ws + (kk + qc) * BSTR + nt * 8 + qr;
                bf[nt][0] = __float_as_uint(bb[0]);
                bf[nt][1] = __float_as_uint(bb[4 * BSTR]);
            }
#pragma unroll
            for (int mt = 0; mt < 4; mt++)
#pragma unroll
                for (int nt = 0; nt < 8; nt++)
                    mma168(acc[mt][nt], af[mt], bf[nt]);
        }
        __syncthreads();
    }

    // register -> global epilogue (bias, optional ReLU)
#pragma unroll
    for (int nt = 0; nt < 8; nt++) {
        const int col = n0 + wn * 64 + nt * 8 + qc * 2;
        const float2 bv = *(const float2*)(bias + col);
#pragma unroll
        for (int mt = 0; mt < 4; mt++) {
            const int row = m0 + wm * 64 + mt * 16 + qr;
            float2 v0 = make_float2(acc[mt][nt][0] + bv.x, acc[mt][nt][1] + bv.y);
            float2 v1 = make_float2(acc[mt][nt][2] + bv.x, acc[mt][nt][3] + bv.y);
            if (EPI == 1) {
                v0.x = fmaxf(v0.x, 0.f); v0.y = fmaxf(v0.y, 0.f);
                v1.x = fmaxf(v1.x, 0.f); v1.y = fmaxf(v1.y, 0.f);
            }
            *(float2*)(C + (size_t)row * N + col)       = v0;
            *(float2*)(C + (size_t)(row + 8) * N + col) = v1;
        }
    }
}

// ============================================================================
// FlashAttention-style dual-source graph attention (unchanged from R4).
// ============================================================================
#define KVSTR 36
#define ATT_F   (2 * 256 * KVSTR)
#define ATT_BM_OFF (ATT_F * 4)
#define ATT_SMEM_BYTES (ATT_BM_OFF + (1024 + 8) * 4)

__global__ __launch_bounds__(256, 2)
void attn_kernel(const float* __restrict__ qkv, const float* __restrict__ kv2,
                 const uint32_t* __restrict__ bm1, const uint32_t* __restrict__ bm2,
                 float* __restrict__ ctx)
{
    extern __shared__ float sm[];
    float* sK = sm;
    float* sV = sK + 256 * KVSTR;
    uint32_t* sBM  = (uint32_t*)((char*)sm + ATT_BM_OFF);
    uint32_t* sBM2 = sBM + 1024;

    const int b  = blockIdx.z;
    const int h  = blockIdx.y;
    const int q0 = blockIdx.x * 128;
    const int tid  = threadIdx.x;
    const int warp = tid >> 5;
    const int lane = tid & 31;
    const int qr   = lane >> 2;
    const int qc   = lane & 3;
    const float scale = 0.17677669529663687f;

#pragma unroll
    for (int j = 0; j < 4; j++) {
        int i = tid + j * 256;
        sBM[i] = bm1[((size_t)(b * CN1) + q0 + (i >> 3)) * 8 + (i & 7)];
    }
    if (tid < 8) sBM2[tid] = bm2[b * 8 + tid];

    uint32_t qf[4][4];
    {
        const float* Qb = qkv + (size_t)(b * CN1 + q0 + warp * 16) * 768 + h * CDH;
#pragma unroll
        for (int kf = 0; kf < 4; kf++) {
            qf[kf][0] = __float_as_uint(Qb[(size_t)qr * 768 + kf * 8 + qc] * scale);
            qf[kf][1] = __float_as_uint(Qb[(size_t)(qr + 8) * 768 + kf * 8 + qc] * scale);
            qf[kf][2] = __float_as_uint(Qb[(size_t)qr * 768 + kf * 8 + qc + 4] * scale);
            qf[kf][3] = __float_as_uint(Qb[(size_t)(qr + 8) * 768 + kf * 8 + qc + 4] * scale);
        }
    }

    float ofin[4][4];
#pragma unroll
    for (int n = 0; n < 4; n++)
#pragma unroll
        for (int e = 0; e < 4; e++) ofin[n][e] = 0.0f;

#pragma unroll 1
    for (int src = 0; src < 2; src++) {
        const float* base = src ? kv2 : qkv;
        const int stride  = src ? 512 : 768;
        const int koff    = src ? 0   : 256;
        const int voff    = src ? 256 : 512;

        __syncthreads();
#pragma unroll
        for (int j = 0; j < 8; j++) {
            int i = tid + j * 256;
            int r = i >> 3, c4 = i & 7;
            const float* row = base + (size_t)(b * 256 + r) * stride + h * CDH + c4 * 4;
            *(float4*)(sK + r * KVSTR + c4 * 4) = *(const float4*)(row + koff);
            *(float4*)(sV + r * KVSTR + c4 * 4) = *(const float4*)(row + voff);
        }
        __syncthreads();

        float m0 = -1e30f, m1 = -1e30f, l0 = 0.0f, l1 = 0.0f;
        float o[4][4];
#pragma unroll
        for (int n = 0; n < 4; n++)
#pragma unroll
            for (int e = 0; e < 4; e++) o[n][e] = 0.0f;

#pragma unroll 1
        for (int chunk = 0; chunk < 4; chunk++) {
            const int key0 = chunk * 64;

            float s[8][4];
#pragma unroll
            for (int nf = 0; nf < 8; nf++) {
                s[nf][0] = s[nf][1] = s[nf][2] = s[nf][3] = 0.0f;
                const float* kb = sK + (size_t)(key0 + nf * 8 + qr) * KVSTR;
#pragma unroll
                for (int kf = 0; kf < 4; kf++) {
                    uint32_t bfr[2];
                    bfr[0] = __float_as_uint(kb[kf * 8 + qc]);
                    bfr[1] = __float_as_uint(kb[kf * 8 + qc + 4]);
                    mma168(s[nf], qf[kf], bfr);
                }
            }

            uint32_t wa0, wa1, wb0, wb1;
            if (src == 0) {
                const uint32_t* ra = sBM + (warp * 16 + qr) * 8 + chunk * 2;
                const uint32_t* rb = sBM + (warp * 16 + qr + 8) * 8 + chunk * 2;
                wa0 = ra[0]; wa1 = ra[1]; wb0 = rb[0]; wb1 = rb[1];
            } else {
                wa0 = sBM2[chunk * 2]; wa1 = sBM2[chunk * 2 + 1];
                wb0 = wa0; wb1 = wa1;
            }
            float cm0 = -1e30f, cm1 = -1e30f;
#pragma unroll
            for (int nf = 0; nf < 8; nf++) {
                const int sh = (nf & 3) * 8 + qc * 2;
                const uint32_t ba = ((nf < 4 ? wa0 : wa1) >> sh);
                const uint32_t bb = ((nf < 4 ? wb0 : wb1) >> sh);
                s[nf][0] = (ba & 1u) ? s[nf][0] : -1e9f;
                s[nf][1] = (ba & 2u) ? s[nf][1] : -1e9f;
                s[nf][2] = (bb & 1u) ? s[nf][2] : -1e9f;
                s[nf][3] = (bb & 2u) ? s[nf][3] : -1e9f;
                cm0 = fmaxf(cm0, fmaxf(s[nf][0], s[nf][1]));
                cm1 = fmaxf(cm1, fmaxf(s[nf][2], s[nf][3]));
            }
            cm0 = fmaxf(cm0, __shfl_xor_sync(0xffffffffu, cm0, 1));
            cm0 = fmaxf(cm0, __shfl_xor_sync(0xffffffffu, cm0, 2));
            cm1 = fmaxf(cm1, __shfl_xor_sync(0xffffffffu, cm1, 1));
            cm1 = fmaxf(cm1, __shfl_xor_sync(0xffffffffu, cm1, 2));

            const float mn0 = fmaxf(m0, cm0), mn1 = fmaxf(m1, cm1);
            const float f0 = __expf(m0 - mn0), f1 = __expf(m1 - mn1);
            m0 = mn0; m1 = mn1;
            l0 *= f0; l1 *= f1;
#pragma unroll
            for (int n = 0; n < 4; n++) {
                o[n][0] *= f0; o[n][1] *= f0;
                o[n][2] *= f1; o[n][3] *= f1;
            }

#pragma unroll
            for (int nf = 0; nf < 8; nf++) {
                s[nf][0] = __expf(s[nf][0] - mn0);
                s[nf][1] = __expf(s[nf][1] - mn0);
                s[nf][2] = __expf(s[nf][2] - mn1);
                s[nf][3] = __expf(s[nf][3] - mn1);
                l0 += s[nf][0] + s[nf][1];
                l1 += s[nf][2] + s[nf][3];
            }

            const int srcA = (lane & ~3) | (qc >> 1);
            const int srcB = srcA + 2;
#pragma unroll
            for (int kfp = 0; kfp < 8; kfp++) {
                float v00 = __shfl_sync(0xffffffffu, s[kfp][0], srcA);
                float v01 = __shfl_sync(0xffffffffu, s[kfp][1], srcA);
                float v20 = __shfl_sync(0xffffffffu, s[kfp][2], srcA);
                float v21 = __shfl_sync(0xffffffffu, s[kfp][3], srcA);
                float v40 = __shfl_sync(0xffffffffu, s[kfp][0], srcB);
                float v41 = __shfl_sync(0xffffffffu, s[kfp][1], srcB);
                float v60 = __shfl_sync(0xffffffffu, s[kfp][2], srcB);
                float v61 = __shfl_sync(0xffffffffu, s[kfp][3], srcB);
                uint32_t af[4];
                af[0] = __float_as_uint((qc & 1) ? v01 : v00);
                af[1] = __float_as_uint((qc & 1) ? v21 : v20);
                af[2] = __float_as_uint((qc & 1) ? v41 : v40);
                af[3] = __float_as_uint((qc & 1) ? v61 : v60);

                const float* vb = sV + (size_t)(key0 + kfp * 8 + qc) * KVSTR;
                const float* vb4 = vb + 4 * KVSTR;
#pragma unroll
                for (int n = 0; n < 4; n++) {
                    uint32_t bfr[2];
                    bfr[0] = __float_as_uint(vb[n * 8 + (lane >> 2)]);
                    bfr[1] = __float_as_uint(vb4[n * 8 + (lane >> 2)]);
                    mma168(o[n], af, bfr);
                }
            }
        }

        l0 += __shfl_xor_sync(0xffffffffu, l0, 1);
        l0 += __shfl_xor_sync(0xffffffffu, l0, 2);
        l1 += __shfl_xor_sync(0xffffffffu, l1, 1);
        l1 += __shfl_xor_sync(0xffffffffu, l1, 2);
        const float i0 = 1.0f / l0, i1 = 1.0f / l1;
#pragma unroll
        for (int n = 0; n < 4; n++) {
            ofin[n][0] += o[n][0] * i0;
            ofin[n][1] += o[n][1] * i0;
            ofin[n][2] += o[n][2] * i1;
            ofin[n][3] += o[n][3] * i1;
        }
    }

    float* outA = ctx + (size_t)(b * CN1 + q0 + warp * 16 + qr) * CD + h * CDH + qc * 2;
    float* outB = outA + 8 * CD;
#pragma unroll
    for (int n = 0; n < 4; n++) {
        *(float2*)(outA + n * 8) = make_float2(ofin[n][0], ofin[n][1]);
        *(float2*)(outB + n * 8) = make_float2(ofin[n][2], ofin[n][3]);
    }
}

// ============================================================================
// out = LayerNorm(X + Y) * g + be
// ============================================================================
__global__ __launch_bounds__(256)
void add_ln_kernel(const float* __restrict__ X, const float* __restrict__ Y,
                   const float* __restrict__ g, const float* __restrict__ be,
                   float* __restrict__ out)
{
    const int warp = threadIdx.x >> 5;
    const int lane = threadIdx.x & 31;
    const size_t row = (size_t)blockIdx.x * 8 + warp;
    const float* x = X + row * CD;
    const float* y = Y + row * CD;
    float v[8];
    float s = 0.0f;
#pragma unroll
    for (int i = 0; i < 8; i++) { v[i] = x[lane + i * 32] + y[lane + i * 32]; s += v[i]; }
#pragma unroll
    for (int o = 16; o > 0; o >>= 1) s += __shfl_xor_sync(0xffffffffu, s, o);
    const float mu = s * (1.0f / CD);
    float s2 = 0.0f;
#pragma unroll
    for (int i = 0; i < 8; i++) { float d = v[i] - mu; s2 += d * d; }
#pragma unroll
    for (int o = 16; o > 0; o >>= 1) s2 += __shfl_xor_sync(0xffffffffu, s2, o);
    const float inv = rsqrtf(s2 * (1.0f / CD) + 1e-6f);
#pragma unroll
    for (int i = 0; i < 8; i++) {
        int c = lane + i * 32;
        out[row * CD + c] = g[c] * (v[i] - mu) * inv + be[c];
    }
}

// ---------------- weight packing + mask bitmaps ----------------
__global__ void pack_qkv(const float* __restrict__ Wq, const float* __restrict__ Wk,
                         const float* __restrict__ Wv, const float* __restrict__ bq,
                         const float* __restrict__ bk, const float* __restrict__ bv,
                         float* __restrict__ Wc, float* __restrict__ bc)
{
    int i = blockIdx.x * 256 + threadIdx.x;
    int r = i >> 8, c = i & 255;
    Wc[r * 768 + c]       = Wq[i];
    Wc[r * 768 + 256 + c] = Wk[i];
    Wc[r * 768 + 512 + c] = Wv[i];
    if (i < 256) { bc[i] = bq[i]; bc[256 + i] = bk[i]; bc[512 + i] = bv[i]; }
}

__global__ void pack_kv(const float* __restrict__ Wk, const float* __restrict__ Wv,
                        const float* __restrict__ bk, const float* __restrict__ bv,
                        float* __restrict__ Wc, float* __restrict__ bc)
{
    int i = blockIdx.x * 256 + threadIdx.x;
    int r = i >> 8, c = i & 255;
    Wc[r * 512 + c]       = Wk[i];
    Wc[r * 512 + 256 + c] = Wv[i];
    if (i < 256) { bc[i] = bk[i]; bc[256 + i] = bv[i]; }
}

__global__ void build_bm1(const float* __restrict__ adj, const float* __restrict__ mask1,
                          uint32_t* __restrict__ bm)
{
    const int gw = (blockIdx.x * blockDim.x + threadIdx.x) >> 5;
    const int lane = threadIdx.x & 31;
    const int b = gw >> 8;
    const float* arow = adj + (size_t)gw * 256;
    const float* m1 = mask1 + (size_t)b * 256;
#pragma unroll
    for (int w = 0; w < 8; w++) {
        float v = arow[w * 32 + lane] * m1[w * 32 + lane];
        uint32_t bits = __ballot_sync(0xffffffffu, v > 0.0f);
        if (lane == 0) bm[(size_t)gw * 8 + w] = bits;
    }
}

__global__ void build_bm2(const float* __restrict__ mask2, uint32_t* __restrict__ bm) {
    const int b = blockIdx.x;
    const int lane = threadIdx.x & 31;
    const int w = threadIdx.x >> 5;
    float v = mask2[(size_t)b * 256 + w * 32 + lane];
    uint32_t bits = __ballot_sync(0xffffffffu, v > 0.0f);
    if (lane == 0) bm[b * 8 + w] = bits;
}

// ============================================================================
// Host launch
// ============================================================================
extern "C" void kernel_launch(void* const* d_in, const int* in_sizes, int n_in,
                              void* d_out, int out_size)
{
    const float* x1    = (const float*)d_in[0];
    const float* adj1  = (const float*)d_in[1];
    const float* mask1 = (const float*)d_in[2];
    const float* x2    = (const float*)d_in[3];
    const float* mask2 = (const float*)d_in[4];
    const float* Wq = (const float*)d_in[5];  const float* bq = (const float*)d_in[6];
    const float* Wk = (const float*)d_in[7];  const float* bk = (const float*)d_in[8];
    const float* Wv = (const float*)d_in[9];  const float* bv = (const float*)d_in[10];
    const float* Wo = (const float*)d_in[11]; const float* bo = (const float*)d_in[12];
    const float* W1 = (const float*)d_in[13]; const float* b1 = (const float*)d_in[14];
    const float* W2 = (const float*)d_in[15]; const float* b2 = (const float*)d_in[16];
    const float* g1 = (const float*)d_in[17]; const float* be1 = (const float*)d_in[18];
    const float* g2 = (const float*)d_in[19]; const float* be2 = (const float*)d_in[20];
    float* out = (float*)d_out;

    float *wqkv, *bqkv, *wkv, *bkv, *qkv, *kv2, *ctx, *tmp, *o1, *hid;
    uint32_t *bm1, *bm2;
    cudaGetSymbolAddress((void**)&wqkv, g_wqkv);
    cudaGetSymbolAddress((void**)&bqkv, g_bqkv);
    cudaGetSymbolAddress((void**)&wkv,  g_wkv);
    cudaGetSymbolAddress((void**)&bkv,  g_bkv);
    cudaGetSymbolAddress((void**)&qkv,  g_qkv);
    cudaGetSymbolAddress((void**)&kv2,  g_kv2);
    cudaGetSymbolAddress((void**)&ctx,  g_ctx);
    cudaGetSymbolAddress((void**)&tmp,  g_tmp);
    cudaGetSymbolAddress((void**)&o1,   g_o1);
    cudaGetSymbolAddress((void**)&hid,  g_hid);
    cudaGetSymbolAddress((void**)&bm1,  g_bm1);
    cudaGetSymbolAddress((void**)&bm2,  g_bm2);

    cudaFuncSetAttribute(gemm_tf32<0>, cudaFuncAttributeMaxDynamicSharedMemorySize, GSMEM_BYTES);
    cudaFuncSetAttribute(gemm_tf32<1>, cudaFuncAttributeMaxDynamicSharedMemorySize, GSMEM_BYTES);
    cudaFuncSetAttribute(attn_kernel,  cudaFuncAttributeMaxDynamicSharedMemorySize, ATT_SMEM_BYTES);

    const int M = CB * CN1;
    dim3 blk(256);
    dim3 gblk(128);

    pack_qkv<<<256, blk>>>(Wq, Wk, Wv, bq, bk, bv, wqkv, bqkv);
    pack_kv <<<256, blk>>>(Wk, Wv, bk, bv, wkv, bkv);
    build_bm1<<<4096, blk>>>(adj1, mask1, bm1);
    build_bm2<<<CB, blk>>>(mask2, bm2);

    gemm_tf32<0><<<dim3(768 / BN, M / BM), gblk, GSMEM_BYTES>>>(x1, wqkv, bqkv, qkv, M, 768, CD);
    gemm_tf32<0><<<dim3(512 / BN, M / BM), gblk, GSMEM_BYTES>>>(x2, wkv,  bkv,  kv2, M, 512, CD);

    attn_kernel<<<dim3(CN1 / 128, CH, CB), blk, ATT_SMEM_BYTES>>>(qkv, kv2, bm1, bm2, ctx);

    gemm_tf32<0><<<dim3(CD / BN, M / BM), gblk, GSMEM_BYTES>>>(ctx, Wo, bo, tmp, M, CD, CD);
    add_ln_kernel<<<M / 8, blk>>>(x1, tmp, g1, be1, o1);

    gemm_tf32<1><<<dim3(CDFF / BN, M / BM), gblk, GSMEM_BYTES>>>(o1, W1, b1, hid, M, CDFF, CD);
    gemm_tf32<0><<<dim3(CD / BN, M / BM), gblk, GSMEM_BYTES>>>(hid, W2, b2, tmp, M, CD, CDFF);
    add_ln_kernel<<<M / 8, blk>>>(o1, tmp, g2, be2, out);
}

// round 6
// speedup vs baseline: 5.0547x; 1.4410x over previous
#include <cuda_runtime.h>
#include <cuda_fp16.h>
#include <cstdint>

#define CB   128
#define CN1  256
#define CN2  256
#define CD   256
#define CH   8
#define CDH  32
#define CDFF 1024

// ---------------- scratch (device globals) ----------------
__device__ __half g_wqkvT[768 * CD];      // [N][K] half, q-part pre-scaled
__device__ __half g_woT  [CD * CD];
__device__ __half g_w1T  [CDFF * CD];
__device__ __half g_w2T  [CD * CDFF];
__device__ float  g_bqkv [768];           // q-part pre-scaled
__device__ __half g_x1h  [CB * CN1 * CD];
__device__ __half g_x2h  [CB * CN2 * CD];
__device__ __half g_qkv  [CB * CN1 * 768];
__device__ __half g_kv2  [CB * CN2 * 512];
__device__ __half g_ctx  [CB * CN1 * CD];
__device__ float  g_tmp  [CB * CN1 * CD];
__device__ float  g_o1f  [CB * CN1 * CD];
__device__ __half g_o1h  [CB * CN1 * CD];
__device__ __half g_hid  [CB * CN1 * CDFF];
__device__ uint32_t g_bm1[CB * CN1 * 8];
__device__ uint32_t g_bm2[CB * 8];

// softmax scale * log2(e), folded into Wq/bq
#define QSCALE (0.17677669529663687f * 1.4426950408889634f)

// ---------------- helpers ----------------
__device__ __forceinline__ void cp16(void* s, const void* g) {
    unsigned sa = (unsigned)__cvta_generic_to_shared(s);
    asm volatile("cp.async.cg.shared.global [%0], [%1], 16;\n" :: "r"(sa), "l"(g));
}
__device__ __forceinline__ void cp_commit() { asm volatile("cp.async.commit_group;\n"); }
template <int N> __device__ __forceinline__ void cp_wait() {
    asm volatile("cp.async.wait_group %0;\n" :: "n"(N));
}
__device__ __forceinline__ void mma16816(float* d, const uint32_t* a, const uint32_t* b) {
    asm volatile(
        "mma.sync.aligned.m16n8k16.row.col.f32.f16.f16.f32 "
        "{%0,%1,%2,%3}, {%4,%5,%6,%7}, {%8,%9}, {%0,%1,%2,%3};"
        : "+f"(d[0]), "+f"(d[1]), "+f"(d[2]), "+f"(d[3])
        : "r"(a[0]), "r"(a[1]), "r"(a[2]), "r"(a[3]), "r"(b[0]), "r"(b[1]));
}
__device__ __forceinline__ float ex2f(float x) {
    float y; asm("ex2.approx.f32 %0, %1;" : "=f"(y) : "f"(x)); return y;
}
__device__ __forceinline__ uint32_t f22u(float a, float b) {
    __half2 h = __floats2half2_rn(a, b);
    return *(uint32_t*)&h;
}
__device__ __forceinline__ uint32_t ldu32h(const __half* p) { return *(const uint32_t*)p; }

// ============================================================================
// fp16 GEMM: C[M,N] = A[M,K](half) @ WT[N,K]^T(half) + bias(f32)
// block 128x128x32, 4 warps, warp 64x64, m16n8k16, 3-stage cp.async.
// EPI: 0 none, 1 ReLU.  OUTH: 1 -> half C, 0 -> float C.
// ============================================================================
#define BM 128
#define BN 128
#define BK 32
#define APADH 40                                  // halves per smem row
#define STGH (2 * 128 * APADH)                    // halves per stage (A+B)
#define GSMEM_BYTES (3 * STGH * 2)                // 61440

template <int EPI, int OUTH>
__global__ __launch_bounds__(128, 2)
void gemm_h(const __half* __restrict__ A, const __half* __restrict__ WT,
            const float* __restrict__ bias, void* __restrict__ Cv,
            int M, int N, int K)
{
    extern __shared__ __half smh[];
    const int tid  = threadIdx.x;
    const int warp = tid >> 5;
    const int lane = tid & 31;
    const int wm   = warp & 1;
    const int wn   = warp >> 1;
    const int m0   = blockIdx.y * BM;
    const int n0   = blockIdx.x * BN;
    const int kt   = K / BK;
    const int qr   = lane >> 2;
    const int qc   = lane & 3;

    auto loadStage = [&](int t) {
        __half* As = smh + (t % 3) * STGH;
        __half* Bs = As + 128 * APADH;
        const int k0 = t * BK;
#pragma unroll
        for (int j = 0; j < 4; j++) {
            int i = tid + j * 128;
            int r = i >> 2, c8 = (i & 3) * 8;
            cp16(As + r * APADH + c8, A + (size_t)(m0 + r) * K + k0 + c8);
        }
#pragma unroll
        for (int j = 0; j < 4; j++) {
            int i = tid + j * 128;
            int r = i >> 2, c8 = (i & 3) * 8;
            cp16(Bs + r * APADH + c8, WT + (size_t)(n0 + r) * K + k0 + c8);
        }
        cp_commit();
    };

    float acc[4][8][4];
#pragma unroll
    for (int mt = 0; mt < 4; mt++)
#pragma unroll
        for (int nt = 0; nt < 8; nt++)
#pragma unroll
            for (int e = 0; e < 4; e++) acc[mt][nt][e] = 0.0f;

    loadStage(0);
    loadStage(1);

    for (int t = 0; t < kt; t++) {
        if (t + 1 < kt) cp_wait<1>(); else cp_wait<0>();
        __syncthreads();
        if (t + 2 < kt) loadStage(t + 2);

        const __half* As = smh + (t % 3) * STGH + (wm * 64) * APADH;
        const __half* Bs = smh + (t % 3) * STGH + 128 * APADH + (wn * 64) * APADH;
#pragma unroll
        for (int kk = 0; kk < BK; kk += 16) {
            uint32_t af[4][4];
            uint32_t bf[8][2];
#pragma unroll
            for (int mt = 0; mt < 4; mt++) {
                const __half* ab = As + (mt * 16 + qr) * APADH + kk + 2 * qc;
                af[mt][0] = ldu32h(ab);
                af[mt][1] = ldu32h(ab + 8 * APADH);
                af[mt][2] = ldu32h(ab + 8);
                af[mt][3] = ldu32h(ab + 8 * APADH + 8);
            }
#pragma unroll
            for (int nt = 0; nt < 8; nt++) {
                const __half* bb = Bs + (nt * 8 + qr) * APADH + kk + 2 * qc;
                bf[nt][0] = ldu32h(bb);
                bf[nt][1] = ldu32h(bb + 8);
            }
#pragma unroll
            for (int mt = 0; mt < 4; mt++)
#pragma unroll
                for (int nt = 0; nt < 8; nt++)
                    mma16816(acc[mt][nt], af[mt], bf[nt]);
        }
        __syncthreads();
    }

    // register -> global epilogue
#pragma unroll
    for (int nt = 0; nt < 8; nt++) {
        const int col = n0 + wn * 64 + nt * 8 + qc * 2;
        const float2 bv = *(const float2*)(bias + col);
#pragma unroll
        for (int mt = 0; mt < 4; mt++) {
            const int row = m0 + wm * 64 + mt * 16 + qr;
            float a0 = acc[mt][nt][0] + bv.x, a1 = acc[mt][nt][1] + bv.y;
            float a2 = acc[mt][nt][2] + bv.x, a3 = acc[mt][nt][3] + bv.y;
            if (EPI == 1) {
                a0 = fmaxf(a0, 0.f); a1 = fmaxf(a1, 0.f);
                a2 = fmaxf(a2, 0.f); a3 = fmaxf(a3, 0.f);
            }
            if (OUTH) {
                __half* C = (__half*)Cv;
                *(uint32_t*)(C + (size_t)row * N + col)       = f22u(a0, a1);
                *(uint32_t*)(C + (size_t)(row + 8) * N + col) = f22u(a2, a3);
            } else {
                float* C = (float*)Cv;
                *(float2*)(C + (size_t)row * N + col)       = make_float2(a0, a1);
                *(float2*)(C + (size_t)(row + 8) * N + col) = make_float2(a2, a3);
            }
        }
    }
}

// ============================================================================
// FlashAttention-style dual-source graph attention, fp16 MMA.
// Grid (N1/128, H, B), 256 threads (8 warps), 16 q-rows per warp.
// ============================================================================
#define KPADH 40
#define VTPAD 264
#define SM_K_H   (256 * KPADH)                 // halves
#define SM_VT_H  (32 * VTPAD)                  // halves
#define ATT_BM_OFF ((SM_K_H + SM_VT_H) * 2)    // bytes
#define ATT_SMEM_BYTES (ATT_BM_OFF + (1024 + 8) * 4)

__global__ __launch_bounds__(256, 2)
void attn_kernel(const __half* __restrict__ qkv, const __half* __restrict__ kv2,
                 const uint32_t* __restrict__ bm1, const uint32_t* __restrict__ bm2,
                 __half* __restrict__ ctx)
{
    extern __shared__ __half smh[];
    __half* sK  = smh;                          // [256][KPADH]
    __half* sVT = sK + SM_K_H;                  // [32][VTPAD]  (dh-major V^T)
    uint32_t* sBM  = (uint32_t*)((char*)smh + ATT_BM_OFF);
    uint32_t* sBM2 = sBM + 1024;

    const int b  = blockIdx.z;
    const int h  = blockIdx.y;
    const int q0 = blockIdx.x * 128;
    const int tid  = threadIdx.x;
    const int warp = tid >> 5;
    const int lane = tid & 31;
    const int qr   = lane >> 2;
    const int qc   = lane & 3;

#pragma unroll
    for (int j = 0; j < 4; j++) {
        int i = tid + j * 256;
        sBM[i] = bm1[((size_t)(b * CN1) + q0 + (i >> 3)) * 8 + (i & 7)];
    }
    if (tid < 8) sBM2[tid] = bm2[b * 8 + tid];

    // Q fragments (scale pre-folded into Wq): 2 k-chunks of 16
    uint32_t qf[2][4];
    {
        const __half* Qb = qkv + (size_t)(b * CN1 + q0 + warp * 16) * 768 + h * CDH;
#pragma unroll
        for (int kc = 0; kc < 2; kc++) {
            const __half* p = Qb + kc * 16 + 2 * qc;
            qf[kc][0] = ldu32h(p + (size_t)qr * 768);
            qf[kc][1] = ldu32h(p + (size_t)(qr + 8) * 768);
            qf[kc][2] = ldu32h(p + (size_t)qr * 768 + 8);
            qf[kc][3] = ldu32h(p + (size_t)(qr + 8) * 768 + 8);
        }
    }

    float ofin[4][4];
#pragma unroll
    for (int n = 0; n < 4; n++)
#pragma unroll
        for (int e = 0; e < 4; e++) ofin[n][e] = 0.0f;

#pragma unroll 1
    for (int src = 0; src < 2; src++) {
        const __half* base = src ? kv2 : qkv;
        const int stride  = src ? 512 : 768;
        const int koff    = src ? 0   : 256;
        const int voff    = src ? 256 : 512;

        __syncthreads();
        // K tile straight; V tile transposed (dh-major)
#pragma unroll
        for (int j = 0; j < 4; j++) {
            int i = tid + j * 256;
            int r = i >> 2, c8 = (i & 3) * 8;
            const __half* row = base + (size_t)(b * 256 + r) * stride + h * CDH;
            *(uint4*)(sK + r * KPADH + c8) = *(const uint4*)(row + koff + c8);
            uint4 vv = *(const uint4*)(row + voff + c8);
            const __half* hv = (const __half*)&vv;
#pragma unroll
            for (int e = 0; e < 8; e++) sVT[(c8 + e) * VTPAD + r] = hv[e];
        }
        __syncthreads();

        float m0 = -1e30f, m1 = -1e30f, l0 = 0.0f, l1 = 0.0f;
        float o[4][4];
#pragma unroll
        for (int n = 0; n < 4; n++)
#pragma unroll
            for (int e = 0; e < 4; e++) o[n][e] = 0.0f;

#pragma unroll 1
        for (int chunk = 0; chunk < 4; chunk++) {
            const int key0 = chunk * 64;

            // ---- S = Q @ K^T : 8 n-frags x 2 k16 steps ----
            float s[8][4];
#pragma unroll
            for (int nf = 0; nf < 8; nf++) {
                s[nf][0] = s[nf][1] = s[nf][2] = s[nf][3] = 0.0f;
                const __half* kb = sK + (size_t)(key0 + nf * 8 + qr) * KPADH + 2 * qc;
#pragma unroll
                for (int kc = 0; kc < 2; kc++) {
                    uint32_t bfr[2];
                    bfr[0] = ldu32h(kb + kc * 16);
                    bfr[1] = ldu32h(kb + kc * 16 + 8);
                    mma16816(s[nf], qf[kc], bfr);
                }
            }

            // ---- mask + chunk max ----
            uint32_t wa0, wa1, wb0, wb1;
            if (src == 0) {
                const uint32_t* ra = sBM + (warp * 16 + qr) * 8 + chunk * 2;
                const uint32_t* rb = sBM + (warp * 16 + qr + 8) * 8 + chunk * 2;
                wa0 = ra[0]; wa1 = ra[1]; wb0 = rb[0]; wb1 = rb[1];
            } else {
                wa0 = sBM2[chunk * 2]; wa1 = sBM2[chunk * 2 + 1];
                wb0 = wa0; wb1 = wa1;
            }
            float cm0 = -1e30f, cm1 = -1e30f;
#pragma unroll
            for (int nf = 0; nf < 8; nf++) {
                const int sh = (nf & 3) * 8 + qc * 2;
                const uint32_t ba = ((nf < 4 ? wa0 : wa1) >> sh);
                const uint32_t bb = ((nf < 4 ? wb0 : wb1) >> sh);
                s[nf][0] = (ba & 1u) ? s[nf][0] : -1e9f;
                s[nf][1] = (ba & 2u) ? s[nf][1] : -1e9f;
                s[nf][2] = (bb & 1u) ? s[nf][2] : -1e9f;
                s[nf][3] = (bb & 2u) ? s[nf][3] : -1e9f;
                cm0 = fmaxf(cm0, fmaxf(s[nf][0], s[nf][1]));
                cm1 = fmaxf(cm1, fmaxf(s[nf][2], s[nf][3]));
            }
            cm0 = fmaxf(cm0, __shfl_xor_sync(0xffffffffu, cm0, 1));
            cm0 = fmaxf(cm0, __shfl_xor_sync(0xffffffffu, cm0, 2));
            cm1 = fmaxf(cm1, __shfl_xor_sync(0xffffffffu, cm1, 1));
            cm1 = fmaxf(cm1, __shfl_xor_sync(0xffffffffu, cm1, 2));

            const float mn0 = fmaxf(m0, cm0), mn1 = fmaxf(m1, cm1);
            const float f0 = ex2f(m0 - mn0), f1 = ex2f(m1 - mn1);
            m0 = mn0; m1 = mn1;
            l0 *= f0; l1 *= f1;
#pragma unroll
            for (int n = 0; n < 4; n++) {
                o[n][0] *= f0; o[n][1] *= f0;
                o[n][2] *= f1; o[n][3] *= f1;
            }

            // ---- P = 2^(S - m) (S already in log2 domain) ----
#pragma unroll
            for (int nf = 0; nf < 8; nf++) {
                s[nf][0] = ex2f(s[nf][0] - mn0);
                s[nf][1] = ex2f(s[nf][1] - mn0);
                s[nf][2] = ex2f(s[nf][2] - mn1);
                s[nf][3] = ex2f(s[nf][3] - mn1);
                l0 += s[nf][0] + s[nf][1];
                l1 += s[nf][2] + s[nf][3];
            }

            // ---- PV: A-frag = packed adjacent S-acc frags (no shuffles) ----
#pragma unroll
            for (int j = 0; j < 4; j++) {
                uint32_t ap[4];
                ap[0] = f22u(s[2*j][0],   s[2*j][1]);
                ap[1] = f22u(s[2*j][2],   s[2*j][3]);
                ap[2] = f22u(s[2*j+1][0], s[2*j+1][1]);
                ap[3] = f22u(s[2*j+1][2], s[2*j+1][3]);
                const int k0j = key0 + j * 16 + 2 * qc;
#pragma unroll
                for (int n = 0; n < 4; n++) {
                    const __half* vb = sVT + (size_t)(n * 8 + qr) * VTPAD + k0j;
                    uint32_t bfr[2];
                    bfr[0] = ldu32h(vb);
                    bfr[1] = ldu32h(vb + 8);
                    mma16816(o[n], ap, bfr);
                }
            }
        }

        l0 += __shfl_xor_sync(0xffffffffu, l0, 1);
        l0 += __shfl_xor_sync(0xffffffffu, l0, 2);
        l1 += __shfl_xor_sync(0xffffffffu, l1, 1);
        l1 += __shfl_xor_sync(0xffffffffu, l1, 2);
        const float i0 = 1.0f / l0, i1 = 1.0f / l1;
#pragma unroll
        for (int n = 0; n < 4; n++) {
            ofin[n][0] += o[n][0] * i0;
            ofin[n][1] += o[n][1] * i0;
            ofin[n][2] += o[n][2] * i1;
            ofin[n][3] += o[n][3] * i1;
        }
    }

    __half* outA = ctx + (size_t)(b * CN1 + q0 + warp * 16 + qr) * CD + h * CDH + qc * 2;
    __half* outB = outA + 8 * CD;
#pragma unroll
    for (int n = 0; n < 4; n++) {
        *(uint32_t*)(outA + n * 8) = f22u(ofin[n][0], ofin[n][1]);
        *(uint32_t*)(outB + n * 8) = f22u(ofin[n][2], ofin[n][3]);
    }
}

// ============================================================================
// out = LayerNorm(X + Y) * g + be   (fp32 math; optional half mirror)
// ============================================================================
template <int WH>
__global__ __launch_bounds__(256)
void add_ln_kernel(const float* __restrict__ X, const float* __restrict__ Y,
                   const float* __restrict__ g, const float* __restrict__ be,
                   float* __restrict__ outF, __half* __restrict__ outH)
{
    const int warp = threadIdx.x >> 5;
    const int lane = threadIdx.x & 31;
    const size_t row = (size_t)blockIdx.x * 8 + warp;
    const float* x = X + row * CD;
    const float* y = Y + row * CD;
    float v[8];
    float s = 0.0f;
#pragma unroll
    for (int i = 0; i < 8; i++) { v[i] = x[lane + i * 32] + y[lane + i * 32]; s += v[i]; }
#pragma unroll
    for (int o = 16; o > 0; o >>= 1) s += __shfl_xor_sync(0xffffffffu, s, o);
    const float mu = s * (1.0f / CD);
    float s2 = 0.0f;
#pragma unroll
    for (int i = 0; i < 8; i++) { float d = v[i] - mu; s2 += d * d; }
#pragma unroll
    for (int o = 16; o > 0; o >>= 1) s2 += __shfl_xor_sync(0xffffffffu, s2, o);
    const float inv = rsqrtf(s2 * (1.0f / CD) + 1e-6f);
#pragma unroll
    for (int i = 0; i < 8; i++) {
        int c = lane + i * 32;
        float r = g[c] * (v[i] - mu) * inv + be[c];
        outF[row * CD + c] = r;
        if (WH) outH[row * CD + c] = __float2half(r);
    }
}

// ============================================================================
// packing: weights -> half transposed [N][K]; x -> half; bias concat; bitmasks
// ============================================================================
__global__ void pack_weights(const float* __restrict__ Wq, const float* __restrict__ Wk,
                             const float* __restrict__ Wv, const float* __restrict__ Wo,
                             const float* __restrict__ W1, const float* __restrict__ W2,
                             __half* __restrict__ wqkvT, __half* __restrict__ woT,
                             __half* __restrict__ w1T,  __half* __restrict__ w2T)
{
    __shared__ float tile[32][33];
    const int z = blockIdx.z;
    const float* src; __half* dst; int K, N; float scale = 1.0f;
    switch (z) {
        case 0: src = Wq; dst = wqkvT;            K = CD;   N = CD;   scale = QSCALE; break;
        case 1: src = Wk; dst = wqkvT + 256 * CD; K = CD;   N = CD;   break;
        case 2: src = Wv; dst = wqkvT + 512 * CD; K = CD;   N = CD;   break;
        case 3: src = Wo; dst = woT;              K = CD;   N = CD;   break;
        case 4: src = W1; dst = w1T;              K = CD;   N = CDFF; break;
        default: src = W2; dst = w2T;             K = CDFF; N = CD;   break;
    }
    const int k0 = blockIdx.y * 32, n0 = blockIdx.x * 32;
    if (k0 >= K || n0 >= N) return;
    const int tx = threadIdx.x, ty = threadIdx.y;
#pragma unroll
    for (int i = 0; i < 32; i += 8) tile[ty + i][tx] = src[(size_t)(k0 + ty + i) * N + n0 + tx];
    __syncthreads();
#pragma unroll
    for (int i = 0; i < 32; i += 8)
        dst[(size_t)(n0 + ty + i) * K + k0 + tx] = __float2half(tile[tx][ty + i] * scale);
}

__global__ void pack_misc(const float* __restrict__ x1, const float* __restrict__ x2,
                          const float* __restrict__ bq, const float* __restrict__ bk,
                          const float* __restrict__ bv,
                          __half* __restrict__ x1h, __half* __restrict__ x2h,
                          float* __restrict__ bqkv)
{
    const size_t i = (size_t)blockIdx.x * 256 + threadIdx.x;
    x1h[i] = __float2half(x1[i]);
    x2h[i] = __float2half(x2[i]);
    if (i < 256) {
        bqkv[i]       = bq[i] * QSCALE;
        bqkv[256 + i] = bk[i];
        bqkv[512 + i] = bv[i];
    }
}

__global__ void build_bm(const float* __restrict__ adj, const float* __restrict__ mask1,
                         const float* __restrict__ mask2,
                         uint32_t* __restrict__ bm1, uint32_t* __restrict__ bm2)
{
    const int lane = threadIdx.x & 31;
    if (blockIdx.x < 4096) {
        const int gw = (blockIdx.x * 256 + threadIdx.x) >> 5;
        const int b = gw >> 8;
        const float* arow = adj + (size_t)gw * 256;
        const float* m1 = mask1 + (size_t)b * 256;
#pragma unroll
        for (int w = 0; w < 8; w++) {
            float v = arow[w * 32 + lane] * m1[w * 32 + lane];
            uint32_t bits = __ballot_sync(0xffffffffu, v > 0.0f);
            if (lane == 0) bm1[(size_t)gw * 8 + w] = bits;
        }
    } else {
        const int b = blockIdx.x - 4096;
        const int w = threadIdx.x >> 5;
        float v = mask2[(size_t)b * 256 + w * 32 + lane];
        uint32_t bits = __ballot_sync(0xffffffffu, v > 0.0f);
        if (lane == 0) bm2[b * 8 + w] = bits;
    }
}

// ============================================================================
// Host launch
// ============================================================================
extern "C" void kernel_launch(void* const* d_in, const int* in_sizes, int n_in,
                              void* d_out, int out_size)
{
    const float* x1    = (const float*)d_in[0];
    const float* adj1  = (const float*)d_in[1];
    const float* mask1 = (const float*)d_in[2];
    const float* x2    = (const float*)d_in[3];
    const float* mask2 = (const float*)d_in[4];
    const float* Wq = (const float*)d_in[5];  const float* bq = (const float*)d_in[6];
    const float* Wk = (const float*)d_in[7];  const float* bk = (const float*)d_in[8];
    const float* Wv = (const float*)d_in[9];  const float* bv = (const float*)d_in[10];
    const float* Wo = (const float*)d_in[11]; const float* bo = (const float*)d_in[12];
    const float* W1 = (const float*)d_in[13]; const float* b1 = (const float*)d_in[14];
    const float* W2 = (const float*)d_in[15]; const float* b2 = (const float*)d_in[16];
    const float* g1 = (const float*)d_in[17]; const float* be1 = (const float*)d_in[18];
    const float* g2 = (const float*)d_in[19]; const float* be2 = (const float*)d_in[20];
    float* out = (float*)d_out;

    __half *wqkvT, *woT, *w1T, *w2T, *x1h, *x2h, *qkv, *kv2, *ctx, *o1h, *hid;
    float *bqkv, *tmp, *o1f;
    uint32_t *bm1, *bm2;
    cudaGetSymbolAddress((void**)&wqkvT, g_wqkvT);
    cudaGetSymbolAddress((void**)&woT,   g_woT);
    cudaGetSymbolAddress((void**)&w1T,   g_w1T);
    cudaGetSymbolAddress((void**)&w2T,   g_w2T);
    cudaGetSymbolAddress((void**)&bqkv,  g_bqkv);
    cudaGetSymbolAddress((void**)&x1h,   g_x1h);
    cudaGetSymbolAddress((void**)&x2h,   g_x2h);
    cudaGetSymbolAddress((void**)&qkv,   g_qkv);
    cudaGetSymbolAddress((void**)&kv2,   g_kv2);
    cudaGetSymbolAddress((void**)&ctx,   g_ctx);
    cudaGetSymbolAddress((void**)&tmp,   g_tmp);
    cudaGetSymbolAddress((void**)&o1f,   g_o1f);
    cudaGetSymbolAddress((void**)&o1h,   g_o1h);
    cudaGetSymbolAddress((void**)&hid,   g_hid);
    cudaGetSymbolAddress((void**)&bm1,   g_bm1);
    cudaGetSymbolAddress((void**)&bm2,   g_bm2);

    cudaFuncSetAttribute(gemm_h<0,1>, cudaFuncAttributeMaxDynamicSharedMemorySize, GSMEM_BYTES);
    cudaFuncSetAttribute(gemm_h<1,1>, cudaFuncAttributeMaxDynamicSharedMemorySize, GSMEM_BYTES);
    cudaFuncSetAttribute(gemm_h<0,0>, cudaFuncAttributeMaxDynamicSharedMemorySize, GSMEM_BYTES);
    cudaFuncSetAttribute(attn_kernel, cudaFuncAttributeMaxDynamicSharedMemorySize, ATT_SMEM_BYTES);

    const int M = CB * CN1;

    // 0: weights
    pack_weights<<<dim3(32, 32, 6), dim3(32, 8)>>>(Wq, Wk, Wv, Wo, W1, W2,
                                                   wqkvT, woT, w1T, w2T);
    // 1: x -> half, bias concat
    pack_misc<<<M * CD / 256, 256>>>(x1, x2, bq, bk, bv, x1h, x2h, bqkv);
    // 2: bitmasks
    build_bm<<<4096 + CB, 256>>>(adj1, mask1, mask2, bm1, bm2);

    // 3: qkv projection (ncu capture slot)
    gemm_h<0,1><<<dim3(6, M / BM), 128, GSMEM_BYTES>>>(x1h, wqkvT, bqkv, qkv, M, 768, CD);
    // 4: kv2 projection
    gemm_h<0,1><<<dim3(4, M / BM), 128, GSMEM_BYTES>>>(x2h, wqkvT + 256 * CD, bqkv + 256,
                                                       kv2, M, 512, CD);
    // 5: attention
    attn_kernel<<<dim3(CN1 / 128, CH, CB), 256, ATT_SMEM_BYTES>>>(qkv, kv2, bm1, bm2, ctx);

    // 6-7: output projection + LN1
    gemm_h<0,0><<<dim3(2, M / BM), 128, GSMEM_BYTES>>>(ctx, woT, bo, tmp, M, CD, CD);
    add_ln_kernel<1><<<M / 8, 256>>>(x1, tmp, g1, be1, o1f, o1h);

    // 8-10: FFN + LN2
    gemm_h<1,1><<<dim3(8, M / BM), 128, GSMEM_BYTES>>>(o1h, w1T, b1, hid, M, CDFF, CD);
    gemm_h<0,0><<<dim3(2, M / BM), 128, GSMEM_BYTES>>>(hid, w2T, b2, tmp, M, CD, CDFF);
    add_ln_kernel<0><<<M / 8, 256>>>(o1f, tmp, g2, be2, out, nullptr);
}

// round 7
// speedup vs baseline: 5.3974x; 1.0678x over previous
#include <cuda_runtime.h>
#include <cuda_fp16.h>
#include <cstdint>

#define CB   128
#define CN1  256
#define CN2  256
#define CD   256
#define CH   8
#define CDH  32
#define CDFF 1024

// ---------------- scratch (device globals) ----------------
__device__ __half g_wqkvT[768 * CD];      // [N][K] half, q-part pre-scaled
__device__ __half g_woT  [CD * CD];
__device__ __half g_w1T  [CDFF * CD];
__device__ __half g_w2T  [CD * CDFF];
__device__ float  g_bqkv [768];
__device__ __half g_x1h  [CB * CN1 * CD];
__device__ __half g_x2h  [CB * CN2 * CD];
__device__ __half g_qkv  [CB * CN1 * 768];
__device__ __half g_kv2  [CB * CN2 * 512];
__device__ __half g_ctx  [CB * CN1 * CD];
__device__ float  g_tmp  [CB * CN1 * CD];
__device__ float  g_o1f  [CB * CN1 * CD];
__device__ __half g_o1h  [CB * CN1 * CD];
__device__ __half g_hid  [CB * CN1 * CDFF];
__device__ uint32_t g_bm1[CB * CN1 * 8];
__device__ uint32_t g_bm2[CB * 8];

#define QSCALE (0.17677669529663687f * 1.4426950408889634f)

// ---------------- helpers ----------------
__device__ __forceinline__ void cp16(void* s, const void* g) {
    unsigned sa = (unsigned)__cvta_generic_to_shared(s);
    asm volatile("cp.async.cg.shared.global [%0], [%1], 16;\n" :: "r"(sa), "l"(g));
}
__device__ __forceinline__ void cp_commit() { asm volatile("cp.async.commit_group;\n"); }
template <int N> __device__ __forceinline__ void cp_wait() {
    asm volatile("cp.async.wait_group %0;\n" :: "n"(N));
}
__device__ __forceinline__ void mma16816(float* d, const uint32_t* a, const uint32_t* b) {
    asm volatile(
        "mma.sync.aligned.m16n8k16.row.col.f32.f16.f16.f32 "
        "{%0,%1,%2,%3}, {%4,%5,%6,%7}, {%8,%9}, {%0,%1,%2,%3};"
        : "+f"(d[0]), "+f"(d[1]), "+f"(d[2]), "+f"(d[3])
        : "r"(a[0]), "r"(a[1]), "r"(a[2]), "r"(a[3]), "r"(b[0]), "r"(b[1]));
}
__device__ __forceinline__ void ldsm4(uint32_t* r, const __half* p) {
    uint32_t a = (uint32_t)__cvta_generic_to_shared(p);
    asm volatile("ldmatrix.sync.aligned.m8n8.x4.shared.b16 {%0,%1,%2,%3}, [%4];"
                 : "=r"(r[0]), "=r"(r[1]), "=r"(r[2]), "=r"(r[3]) : "r"(a));
}
__device__ __forceinline__ void ldsm4t(uint32_t* r, const __half* p) {
    uint32_t a = (uint32_t)__cvta_generic_to_shared(p);
    asm volatile("ldmatrix.sync.aligned.m8n8.x4.trans.shared.b16 {%0,%1,%2,%3}, [%4];"
                 : "=r"(r[0]), "=r"(r[1]), "=r"(r[2]), "=r"(r[3]) : "r"(a));
}
__device__ __forceinline__ float ex2f(float x) {
    float y; asm("ex2.approx.f32 %0, %1;" : "=f"(y) : "f"(x)); return y;
}
__device__ __forceinline__ uint32_t f22u(float a, float b) {
    __half2 h = __floats2half2_rn(a, b);
    return *(uint32_t*)&h;
}

// ============================================================================
// fp16 GEMM: block 128x128x32, 4 warps, warp 64x64, m16n8k16,
// ldmatrix fragment loads, 4-stage cp.async, 1 barrier/iter.
// ============================================================================
#define BM 128
#define BN 128
#define BK 32
#define APADH 40
#define STGH (2 * 128 * APADH)
#define GS 4
#define GSMEM_BYTES (GS * STGH * 2)               // 81920

template <int EPI, int OUTH>
__global__ __launch_bounds__(128, 2)
void gemm_h(const __half* __restrict__ A, const __half* __restrict__ WT,
            const float* __restrict__ bias, void* __restrict__ Cv,
            int M, int N, int K)
{
    extern __shared__ __half smh[];
    const int tid  = threadIdx.x;
    const int warp = tid >> 5;
    const int lane = tid & 31;
    const int wm   = warp & 1;
    const int wn   = warp >> 1;
    const int m0   = blockIdx.y * BM;
    const int n0   = blockIdx.x * BN;
    const int kt   = K / BK;
    const int qr   = lane >> 2;
    const int qc   = lane & 3;
    // ldmatrix lane address components
    const int arow = (lane & 7) + 8 * ((lane >> 3) & 1);
    const int acol = 8 * (lane >> 4);
    const int brow = (lane & 7) + 8 * (lane >> 4);
    const int bcol = 8 * ((lane >> 3) & 1);

    auto loadStage = [&](int t) {
        __half* As = smh + (t & (GS - 1)) * STGH;
        __half* Bs = As + 128 * APADH;
        const int k0 = t * BK;
#pragma unroll
        for (int j = 0; j < 4; j++) {
            int i = tid + j * 128;
            int r = i >> 2, c8 = (i & 3) * 8;
            cp16(As + r * APADH + c8, A + (size_t)(m0 + r) * K + k0 + c8);
        }
#pragma unroll
        for (int j = 0; j < 4; j++) {
            int i = tid + j * 128;
            int r = i >> 2, c8 = (i & 3) * 8;
            cp16(Bs + r * APADH + c8, WT + (size_t)(n0 + r) * K + k0 + c8);
        }
        cp_commit();
    };

    float acc[4][8][4];
#pragma unroll
    for (int mt = 0; mt < 4; mt++)
#pragma unroll
        for (int nt = 0; nt < 8; nt++)
#pragma unroll
            for (int e = 0; e < 4; e++) acc[mt][nt][e] = 0.0f;

    loadStage(0);
    loadStage(1);
    loadStage(2);

    for (int t = 0; t < kt; t++) {
        if (t + 2 < kt)      cp_wait<2>();
        else if (t + 1 < kt) cp_wait<1>();
        else                 cp_wait<0>();
        __syncthreads();
        if (t + 3 < kt) loadStage(t + 3);

        const __half* As = smh + (t & (GS - 1)) * STGH + (wm * 64) * APADH;
        const __half* Bs = smh + (t & (GS - 1)) * STGH + 128 * APADH + (wn * 64) * APADH;
#pragma unroll
        for (int kk = 0; kk < BK; kk += 16) {
            uint32_t af[4][4];
            uint32_t bf[4][4];
#pragma unroll
            for (int mt = 0; mt < 4; mt++)
                ldsm4(af[mt], As + (mt * 16 + arow) * APADH + kk + acol);
#pragma unroll
            for (int p = 0; p < 4; p++)
                ldsm4(bf[p], Bs + (p * 16 + brow) * APADH + kk + bcol);
#pragma unroll
            for (int mt = 0; mt < 4; mt++)
#pragma unroll
                for (int nt = 0; nt < 8; nt++)
                    mma16816(acc[mt][nt], af[mt], &bf[nt >> 1][(nt & 1) * 2]);
        }
    }

    // register -> global epilogue
#pragma unroll
    for (int nt = 0; nt < 8; nt++) {
        const int col = n0 + wn * 64 + nt * 8 + qc * 2;
        const float2 bv = *(const float2*)(bias + col);
#pragma unroll
        for (int mt = 0; mt < 4; mt++) {
            const int row = m0 + wm * 64 + mt * 16 + qr;
            float a0 = acc[mt][nt][0] + bv.x, a1 = acc[mt][nt][1] + bv.y;
            float a2 = acc[mt][nt][2] + bv.x, a3 = acc[mt][nt][3] + bv.y;
            if (EPI == 1) {
                a0 = fmaxf(a0, 0.f); a1 = fmaxf(a1, 0.f);
                a2 = fmaxf(a2, 0.f); a3 = fmaxf(a3, 0.f);
            }
            if (OUTH) {
                __half* C = (__half*)Cv;
                *(uint32_t*)(C + (size_t)row * N + col)       = f22u(a0, a1);
                *(uint32_t*)(C + (size_t)(row + 8) * N + col) = f22u(a2, a3);
            } else {
                float* C = (float*)Cv;
                *(float2*)(C + (size_t)row * N + col)       = make_float2(a0, a1);
                *(float2*)(C + (size_t)(row + 8) * N + col) = make_float2(a2, a3);
            }
        }
    }
}

// ============================================================================
// FlashAttention-style dual-source graph attention, fp16 MMA + ldmatrix.
// ============================================================================
#define KPADH 40
#define SM_K_H   (256 * KPADH)
#define SM_V_H   (256 * KPADH)
#define ATT_BM_OFF ((SM_K_H + SM_V_H) * 2)
#define ATT_SMEM_BYTES (ATT_BM_OFF + (1024 + 8) * 4)

__global__ __launch_bounds__(256, 2)
void attn_kernel(const __half* __restrict__ qkv, const __half* __restrict__ kv2,
                 const uint32_t* __restrict__ bm1, const uint32_t* __restrict__ bm2,
                 __half* __restrict__ ctx)
{
    extern __shared__ __half smh[];
    __half* sK = smh;                           // [256][KPADH]
    __half* sV = sK + SM_K_H;                   // [256][KPADH]
    uint32_t* sBM  = (uint32_t*)((char*)smh + ATT_BM_OFF);
    uint32_t* sBM2 = sBM + 1024;

    const int b  = blockIdx.z;
    const int h  = blockIdx.y;
    const int q0 = blockIdx.x * 128;
    const int tid  = threadIdx.x;
    const int warp = tid >> 5;
    const int lane = tid & 31;
    const int qr   = lane >> 2;
    const int qc   = lane & 3;
    const int arow = (lane & 7) + 8 * ((lane >> 3) & 1);
    const int acol = 8 * (lane >> 4);
    const int brow = (lane & 7) + 8 * (lane >> 4);
    const int bcol = 8 * ((lane >> 3) & 1);

#pragma unroll
    for (int j = 0; j < 4; j++) {
        int i = tid + j * 256;
        sBM[i] = bm1[((size_t)(b * CN1) + q0 + (i >> 3)) * 8 + (i & 7)];
    }
    if (tid < 8) sBM2[tid] = bm2[b * 8 + tid];

    // Q fragments (scale pre-folded into Wq)
    uint32_t qf[2][4];
    {
        const __half* Qb = qkv + (size_t)(b * CN1 + q0 + warp * 16) * 768 + h * CDH;
#pragma unroll
        for (int kc = 0; kc < 2; kc++) {
            const __half* p = Qb + kc * 16 + 2 * qc;
            qf[kc][0] = *(const uint32_t*)(p + (size_t)qr * 768);
            qf[kc][1] = *(const uint32_t*)(p + (size_t)(qr + 8) * 768);
            qf[kc][2] = *(const uint32_t*)(p + (size_t)qr * 768 + 8);
            qf[kc][3] = *(const uint32_t*)(p + (size_t)(qr + 8) * 768 + 8);
        }
    }

    float ofin[4][4];
#pragma unroll
    for (int n = 0; n < 4; n++)
#pragma unroll
        for (int e = 0; e < 4; e++) ofin[n][e] = 0.0f;

#pragma unroll 1
    for (int src = 0; src < 2; src++) {
        const __half* base = src ? kv2 : qkv;
        const int stride  = src ? 512 : 768;
        const int koff    = src ? 0   : 256;
        const int voff    = src ? 256 : 512;

        __syncthreads();
#pragma unroll
        for (int j = 0; j < 4; j++) {
            int i = tid + j * 256;
            int r = i >> 2, c8 = (i & 3) * 8;
            const __half* row = base + (size_t)(b * 256 + r) * stride + h * CDH;
            *(uint4*)(sK + r * KPADH + c8) = *(const uint4*)(row + koff + c8);
            *(uint4*)(sV + r * KPADH + c8) = *(const uint4*)(row + voff + c8);
        }
        __syncthreads();

        float m0 = -1e30f, m1 = -1e30f, l0 = 0.0f, l1 = 0.0f;
        float o[4][4];
#pragma unroll
        for (int n = 0; n < 4; n++)
#pragma unroll
            for (int e = 0; e < 4; e++) o[n][e] = 0.0f;

#pragma unroll 1
        for (int chunk = 0; chunk < 4; chunk++) {
            const int key0 = chunk * 64;

            // ---- S = Q @ K^T : ldmatrix B frags, 8 nf via 4 pair-calls ----
            float s[8][4];
#pragma unroll
            for (int nf = 0; nf < 8; nf++)
                s[nf][0] = s[nf][1] = s[nf][2] = s[nf][3] = 0.0f;
#pragma unroll
            for (int pr = 0; pr < 4; pr++) {
                const __half* kbase = sK + (size_t)(key0 + pr * 16 + brow) * KPADH + bcol;
                uint32_t kb0[4], kb1[4];
                ldsm4(kb0, kbase);          // k halves 0-15
                ldsm4(kb1, kbase + 16);     // k halves 16-31
                mma16816(s[2 * pr],     qf[0], kb0 + 0);
                mma16816(s[2 * pr],     qf[1], kb1 + 0);
                mma16816(s[2 * pr + 1], qf[0], kb0 + 2);
                mma16816(s[2 * pr + 1], qf[1], kb1 + 2);
            }

            // ---- mask + chunk max ----
            uint32_t wa0, wa1, wb0, wb1;
            if (src == 0) {
                const uint32_t* ra = sBM + (warp * 16 + qr) * 8 + chunk * 2;
                const uint32_t* rb = sBM + (warp * 16 + qr + 8) * 8 + chunk * 2;
                wa0 = ra[0]; wa1 = ra[1]; wb0 = rb[0]; wb1 = rb[1];
            } else {
                wa0 = sBM2[chunk * 2]; wa1 = sBM2[chunk * 2 + 1];
                wb0 = wa0; wb1 = wa1;
            }
            float cm0 = -1e30f, cm1 = -1e30f;
#pragma unroll
            for (int nf = 0; nf < 8; nf++) {
                const int sh = (nf & 3) * 8 + qc * 2;
                const uint32_t ba = ((nf < 4 ? wa0 : wa1) >> sh);
                const uint32_t bb = ((nf < 4 ? wb0 : wb1) >> sh);
                s[nf][0] = (ba & 1u) ? s[nf][0] : -1e9f;
                s[nf][1] = (ba & 2u) ? s[nf][1] : -1e9f;
                s[nf][2] = (bb & 1u) ? s[nf][2] : -1e9f;
                s[nf][3] = (bb & 2u) ? s[nf][3] : -1e9f;
                cm0 = fmaxf(cm0, fmaxf(s[nf][0], s[nf][1]));
                cm1 = fmaxf(cm1, fmaxf(s[nf][2], s[nf][3]));
            }
            cm0 = fmaxf(cm0, __shfl_xor_sync(0xffffffffu, cm0, 1));
            cm0 = fmaxf(cm0, __shfl_xor_sync(0xffffffffu, cm0, 2));
            cm1 = fmaxf(cm1, __shfl_xor_sync(0xffffffffu, cm1, 1));
            cm1 = fmaxf(cm1, __shfl_xor_sync(0xffffffffu, cm1, 2));

            const float mn0 = fmaxf(m0, cm0), mn1 = fmaxf(m1, cm1);
            const float f0 = ex2f(m0 - mn0), f1 = ex2f(m1 - mn1);
            m0 = mn0; m1 = mn1;
            l0 *= f0; l1 *= f1;
#pragma unroll
            for (int n = 0; n < 4; n++) {
                o[n][0] *= f0; o[n][1] *= f0;
                o[n][2] *= f1; o[n][3] *= f1;
            }

#pragma unroll
            for (int nf = 0; nf < 8; nf++) {
                s[nf][0] = ex2f(s[nf][0] - mn0);
                s[nf][1] = ex2f(s[nf][1] - mn0);
                s[nf][2] = ex2f(s[nf][2] - mn1);
                s[nf][3] = ex2f(s[nf][3] - mn1);
                l0 += s[nf][0] + s[nf][1];
                l1 += s[nf][2] + s[nf][3];
            }

            // ---- PV: P a-frags from S accs; V b-frags via ldmatrix.trans ----
#pragma unroll
            for (int j = 0; j < 4; j++) {
                uint32_t ap[4];
                ap[0] = f22u(s[2*j][0],   s[2*j][1]);
                ap[1] = f22u(s[2*j][2],   s[2*j][3]);
                ap[2] = f22u(s[2*j+1][0], s[2*j+1][1]);
                ap[3] = f22u(s[2*j+1][2], s[2*j+1][3]);
                const __half* vbase = sV + (size_t)(key0 + j * 16 + arow) * KPADH + acol;
                uint32_t vb0[4], vb1[4];
                ldsm4t(vb0, vbase);         // dh 0-15
                ldsm4t(vb1, vbase + 16);    // dh 16-31
                mma16816(o[0], ap, vb0 + 0);
                mma16816(o[1], ap, vb0 + 2);
                mma16816(o[2], ap, vb1 + 0);
                mma16816(o[3], ap, vb1 + 2);
            }
        }

        l0 += __shfl_xor_sync(0xffffffffu, l0, 1);
        l0 += __shfl_xor_sync(0xffffffffu, l0, 2);
        l1 += __shfl_xor_sync(0xffffffffu, l1, 1);
        l1 += __shfl_xor_sync(0xffffffffu, l1, 2);
        const float i0 = 1.0f / l0, i1 = 1.0f / l1;
#pragma unroll
        for (int n = 0; n < 4; n++) {
            ofin[n][0] += o[n][0] * i0;
            ofin[n][1] += o[n][1] * i0;
            ofin[n][2] += o[n][2] * i1;
            ofin[n][3] += o[n][3] * i1;
        }
    }

    __half* outA = ctx + (size_t)(b * CN1 + q0 + warp * 16 + qr) * CD + h * CDH + qc * 2;
    __half* outB = outA + 8 * CD;
#pragma unroll
    for (int n = 0; n < 4; n++) {
        *(uint32_t*)(outA + n * 8) = f22u(ofin[n][0], ofin[n][1]);
        *(uint32_t*)(outB + n * 8) = f22u(ofin[n][2], ofin[n][3]);
    }
}

// ============================================================================
// out = LayerNorm(X + Y) * g + be   (fp32 math; optional half mirror)
// ============================================================================
template <int WH>
__global__ __launch_bounds__(256)
void add_ln_kernel(const float* __restrict__ X, const float* __restrict__ Y,
                   const float* __restrict__ g, const float* __restrict__ be,
                   float* __restrict__ outF, __half* __restrict__ outH)
{
    const int warp = threadIdx.x >> 5;
    const int lane = threadIdx.x & 31;
    const size_t row = (size_t)blockIdx.x * 8 + warp;
    const float* x = X + row * CD;
    const float* y = Y + row * CD;
    float v[8];
    float s = 0.0f;
#pragma unroll
    for (int i = 0; i < 8; i++) { v[i] = x[lane + i * 32] + y[lane + i * 32]; s += v[i]; }
#pragma unroll
    for (int o = 16; o > 0; o >>= 1) s += __shfl_xor_sync(0xffffffffu, s, o);
    const float mu = s * (1.0f / CD);
    float s2 = 0.0f;
#pragma unroll
    for (int i = 0; i < 8; i++) { float d = v[i] - mu; s2 += d * d; }
#pragma unroll
    for (int o = 16; o > 0; o >>= 1) s2 += __shfl_xor_sync(0xffffffffu, s2, o);
    const float inv = rsqrtf(s2 * (1.0f / CD) + 1e-6f);
#pragma unroll
    for (int i = 0; i < 8; i++) {
        int c = lane + i * 32;
        float r = g[c] * (v[i] - mu) * inv + be[c];
        outF[row * CD + c] = r;
        if (WH) outH[row * CD + c] = __float2half(r);
    }
}

// ============================================================================
// packing kernels (unchanged from R6)
// ============================================================================
__global__ void pack_weights(const float* __restrict__ Wq, const float* __restrict__ Wk,
                             const float* __restrict__ Wv, const float* __restrict__ Wo,
                             const float* __restrict__ W1, const float* __restrict__ W2,
                             __half* __restrict__ wqkvT, __half* __restrict__ woT,
                             __half* __restrict__ w1T,  __half* __restrict__ w2T)
{
    __shared__ float tile[32][33];
    const int z = blockIdx.z;
    const float* src; __half* dst; int K, N; float scale = 1.0f;
    switch (z) {
        case 0: src = Wq; dst = wqkvT;            K = CD;   N = CD;   scale = QSCALE; break;
        case 1: src = Wk; dst = wqkvT + 256 * CD; K = CD;   N = CD;   break;
        case 2: src = Wv; dst = wqkvT + 512 * CD; K = CD;   N = CD;   break;
        case 3: src = Wo; dst = woT;              K = CD;   N = CD;   break;
        case 4: src = W1; dst = w1T;              K = CD;   N = CDFF; break;
        default: src = W2; dst = w2T;             K = CDFF; N = CD;   break;
    }
    const int k0 = blockIdx.y * 32, n0 = blockIdx.x * 32;
    if (k0 >= K || n0 >= N) return;
    const int tx = threadIdx.x, ty = threadIdx.y;
#pragma unroll
    for (int i = 0; i < 32; i += 8) tile[ty + i][tx] = src[(size_t)(k0 + ty + i) * N + n0 + tx];
    __syncthreads();
#pragma unroll
    for (int i = 0; i < 32; i += 8)
        dst[(size_t)(n0 + ty + i) * K + k0 + tx] = __float2half(tile[tx][ty + i] * scale);
}

__global__ void pack_misc(const float* __restrict__ x1, const float* __restrict__ x2,
                          const float* __restrict__ bq, const float* __restrict__ bk,
                          const float* __restrict__ bv,
                          __half* __restrict__ x1h, __half* __restrict__ x2h,
                          float* __restrict__ bqkv)
{
    const size_t i = (size_t)blockIdx.x * 256 + threadIdx.x;
    x1h[i] = __float2half(x1[i]);
    x2h[i] = __float2half(x2[i]);
    if (i < 256) {
        bqkv[i]       = bq[i] * QSCALE;
        bqkv[256 + i] = bk[i];
        bqkv[512 + i] = bv[i];
    }
}

__global__ void build_bm(const float* __restrict__ adj, const float* __restrict__ mask1,
                         const float* __restrict__ mask2,
                         uint32_t* __restrict__ bm1, uint32_t* __restrict__ bm2)
{
    const int lane = threadIdx.x & 31;
    if (blockIdx.x < 4096) {
        const int gw = (blockIdx.x * 256 + threadIdx.x) >> 5;
        const int b = gw >> 8;
        const float* arow = adj + (size_t)gw * 256;
        const float* m1 = mask1 + (size_t)b * 256;
#pragma unroll
        for (int w = 0; w < 8; w++) {
            float v = arow[w * 32 + lane] * m1[w * 32 + lane];
            uint32_t bits = __ballot_sync(0xffffffffu, v > 0.0f);
            if (lane == 0) bm1[(size_t)gw * 8 + w] = bits;
        }
    } else {
        const int b = blockIdx.x - 4096;
        const int w = threadIdx.x >> 5;
        float v = mask2[(size_t)b * 256 + w * 32 + lane];
        uint32_t bits = __ballot_sync(0xffffffffu, v > 0.0f);
        if (lane == 0) bm2[b * 8 + w] = bits;
    }
}

// ============================================================================
// Host launch
// ============================================================================
extern "C" void kernel_launch(void* const* d_in, const int* in_sizes, int n_in,
                              void* d_out, int out_size)
{
    const float* x1    = (const float*)d_in[0];
    const float* adj1  = (const float*)d_in[1];
    const float* mask1 = (const float*)d_in[2];
    const float* x2    = (const float*)d_in[3];
    const float* mask2 = (const float*)d_in[4];
    const float* Wq = (const float*)d_in[5];  const float* bq = (const float*)d_in[6];
    const float* Wk = (const float*)d_in[7];  const float* bk = (const float*)d_in[8];
    const float* Wv = (const float*)d_in[9];  const float* bv = (const float*)d_in[10];
    const float* Wo = (const float*)d_in[11]; const float* bo = (const float*)d_in[12];
    const float* W1 = (const float*)d_in[13]; const float* b1 = (const float*)d_in[14];
    const float* W2 = (const float*)d_in[15]; const float* b2 = (const float*)d_in[16];
    const float* g1 = (const float*)d_in[17]; const float* be1 = (const float*)d_in[18];
    const float* g2 = (const float*)d_in[19]; const float* be2 = (const float*)d_in[20];
    float* out = (float*)d_out;

    __half *wqkvT, *woT, *w1T, *w2T, *x1h, *x2h, *qkv, *kv2, *ctx, *o1h, *hid;
    float *bqkv, *tmp, *o1f;
    uint32_t *bm1, *bm2;
    cudaGetSymbolAddress((void**)&wqkvT, g_wqkvT);
    cudaGetSymbolAddress((void**)&woT,   g_woT);
    cudaGetSymbolAddress((void**)&w1T,   g_w1T);
    cudaGetSymbolAddress((void**)&w2T,   g_w2T);
    cudaGetSymbolAddress((void**)&bqkv,  g_bqkv);
    cudaGetSymbolAddress((void**)&x1h,   g_x1h);
    cudaGetSymbolAddress((void**)&x2h,   g_x2h);
    cudaGetSymbolAddress((void**)&qkv,   g_qkv);
    cudaGetSymbolAddress((void**)&kv2,   g_kv2);
    cudaGetSymbolAddress((void**)&ctx,   g_ctx);
    cudaGetSymbolAddress((void**)&tmp,   g_tmp);
    cudaGetSymbolAddress((void**)&o1f,   g_o1f);
    cudaGetSymbolAddress((void**)&o1h,   g_o1h);
    cudaGetSymbolAddress((void**)&hid,   g_hid);
    cudaGetSymbolAddress((void**)&bm1,   g_bm1);
    cudaGetSymbolAddress((void**)&bm2,   g_bm2);

    cudaFuncSetAttribute(gemm_h<0,1>, cudaFuncAttributeMaxDynamicSharedMemorySize, GSMEM_BYTES);
    cudaFuncSetAttribute(gemm_h<1,1>, cudaFuncAttributeMaxDynamicSharedMemorySize, GSMEM_BYTES);
    cudaFuncSetAttribute(gemm_h<0,0>, cudaFuncAttributeMaxDynamicSharedMemorySize, GSMEM_BYTES);
    cudaFuncSetAttribute(attn_kernel, cudaFuncAttributeMaxDynamicSharedMemorySize, ATT_SMEM_BYTES);

    const int M = CB * CN1;

    pack_weights<<<dim3(32, 32, 6), dim3(32, 8)>>>(Wq, Wk, Wv, Wo, W1, W2,
                                                   wqkvT, woT, w1T, w2T);
    pack_misc<<<M * CD / 256, 256>>>(x1, x2, bq, bk, bv, x1h, x2h, bqkv);
    build_bm<<<4096 + CB, 256>>>(adj1, mask1, mask2, bm1, bm2);

    // launch idx 3: qkv projection (ncu capture slot)
    gemm_h<0,1><<<dim3(6, M / BM), 128, GSMEM_BYTES>>>(x1h, wqkvT, bqkv, qkv, M, 768, CD);
    gemm_h<0,1><<<dim3(4, M / BM), 128, GSMEM_BYTES>>>(x2h, wqkvT + 256 * CD, bqkv + 256,
                                                       kv2, M, 512, CD);
    attn_kernel<<<dim3(CN1 / 128, CH, CB), 256, ATT_SMEM_BYTES>>>(qkv, kv2, bm1, bm2, ctx);

    gemm_h<0,0><<<dim3(2, M / BM), 128, GSMEM_BYTES>>>(ctx, woT, bo, tmp, M, CD, CD);
    add_ln_kernel<1><<<M / 8, 256>>>(x1, tmp, g1, be1, o1f, o1h);

    gemm_h<1,1><<<dim3(8, M / BM), 128, GSMEM_BYTES>>>(o1h, w1T, b1, hid, M, CDFF, CD);
    gemm_h<0,0><<<dim3(2, M / BM), 128, GSMEM_BYTES>>>(hid, w2T, b2, tmp, M, CD, CDFF);
    add_ln_kernel<0><<<M / 8, 256>>>(o1f, tmp, g2, be2, out, nullptr);
}